// round 7
// baseline (speedup 1.0000x reference)
#include <cuda_runtime.h>
#include <cuda_bf16.h>
#include <math.h>

// RNN-T greedy decode, persistent kernel. LSTM/pred fp32; joint bf16 + exact fp32 re-check.
#define B 8
#define T 200
#define H 1024
#define NV 16385
#define BLANK 16384
#define MAXSYM 4
#define NSTEP (T * MAXSYM) // 800
#define G 148
#define NTHR 512
#define JTILE 112          // vocab cols per block in joint (148*112 = 16576 >= NV)
#define DELTA 0.0625f

// ---------------- device scratch ----------------
__device__ __align__(16) float g_encT[T * B * H];
__device__ __align__(16) float g_E[T * B * H];
__device__ __align__(16) unsigned short g_WoutB[(size_t)G * 1024 * JTILE + 64]; // bf16 tiles [tile][k][112]
__device__ __align__(16) float g_WoutV[(size_t)16416 * 1024];                   // fp32 [v][k] for re-check
__device__ __align__(16) float g_Wl[(size_t)128 * 1024 * 64 + 128];
__device__ __align__(16) float g_WpT[H * H];
__device__ float g_h[B * H];
__device__ float g_c[B * H];
__device__ float g_h2[2][B * H];
__device__ float g_c2[2][B * H];
__device__ float g_qkb[H * B];     // q in [j][b]
__device__ float g_qbj[B * H];     // q in [b][j] (for re-check dot)
__device__ int   g_lastbuf[2][B];
__device__ int   g_advbuf[2][B];
__device__ unsigned g_amax32[B];               // bf16-stage max (encoded float)
__device__ unsigned long long g_afin[B];       // fp32 re-checked argmax keys
__device__ unsigned g_leaf[8];
__device__ unsigned g_root;
__device__ unsigned g_gen;

// ---------------- helpers ----------------
__device__ __forceinline__ unsigned long long ffma2(unsigned long long a,
                                                    unsigned long long b,
                                                    unsigned long long c) {
    unsigned long long d;
    asm("fma.rn.f32x2 %0, %1, %2, %3;" : "=l"(d) : "l"(a), "l"(b), "l"(c));
    return d;
}
__device__ __forceinline__ unsigned long long dup2(float w) {
    unsigned long long r;
    unsigned u = __float_as_uint(w);
    asm("mov.b64 %0, {%1, %1};" : "=l"(r) : "r"(u));
    return r;
}
__device__ __forceinline__ unsigned long long dup2lo(unsigned a) {
    unsigned f = a << 16; unsigned long long r;
    asm("mov.b64 %0, {%1, %1};" : "=l"(r) : "r"(f));
    return r;
}
__device__ __forceinline__ unsigned long long dup2hi(unsigned a) {
    unsigned f = a & 0xFFFF0000u; unsigned long long r;
    asm("mov.b64 %0, {%1, %1};" : "=l"(r) : "r"(f));
    return r;
}
__device__ __forceinline__ unsigned long long pack_key(float f, int v) {
    unsigned u = __float_as_uint(f);
    u = (u & 0x80000000u) ? ~u : (u | 0x80000000u);
    return ((unsigned long long)u << 32) | (unsigned)(BLANK - v);
}
__device__ __forceinline__ unsigned enc32(float f) {
    unsigned u = __float_as_uint(f);
    return (u & 0x80000000u) ? ~u : (u | 0x80000000u);
}
__device__ __forceinline__ float dec_key32(unsigned e) {
    unsigned u = (e & 0x80000000u) ? (e ^ 0x80000000u) : ~e;
    return __uint_as_float(u);
}
__device__ __forceinline__ float sigm(float x) { return 1.0f / (1.0f + expf(-x)); }

__device__ __forceinline__ void cp16(unsigned dst, const void* src) {
    asm volatile("cp.async.cg.shared.global [%0], [%1], 16;" :: "r"(dst), "l"(src));
}
__device__ __forceinline__ void cp_commit() { asm volatile("cp.async.commit_group;"); }
__device__ __forceinline__ void cp_wait1()  { asm volatile("cp.async.wait_group 1;"); }
__device__ __forceinline__ void cp_wait0()  { asm volatile("cp.async.wait_group 0;"); }

__device__ __forceinline__ void grid_sync(int bid) {
    __syncthreads();
    if (threadIdx.x == 0) {
        __threadfence();
        unsigned gen = *(volatile unsigned*)&g_gen;
        int leaf = bid & 7;
        unsigned cnt = (leaf < 4) ? 19u : 18u;
        unsigned t = atomicAdd(&g_leaf[leaf], 1u);
        if ((t % cnt) == cnt - 1u) {
            unsigned rt = atomicAdd(&g_root, 1u);
            if ((rt & 7u) == 7u) {
                __threadfence();
                atomicExch(&g_gen, gen + 1u);
            }
        }
        while (*(volatile unsigned*)&g_gen == gen) {}
        __threadfence();
    }
    __syncthreads();
}

// ---------------- setup kernels ----------------
__global__ void k_setup1(const float* __restrict__ enc, const float* __restrict__ W_pred) {
    __shared__ float tile[32][33];
    int bidx = blockIdx.x;
    int tx = threadIdx.x, ty = threadIdx.y;   // 32 x 8
    if (bidx < 1792) {
        int b = bidx & 7, kb = ((bidx >> 3) & 31) * 32, tb = (bidx >> 8) * 32;
#pragma unroll
        for (int i = 0; i < 4; i++) {
            int k = kb + ty + i * 8, t = tb + tx;
            tile[ty + i * 8][tx] = (t < T) ? enc[(size_t)b * H * T + (size_t)k * T + t] : 0.0f;
        }
        __syncthreads();
#pragma unroll
        for (int i = 0; i < 4; i++) {
            int t = tb + ty + i * 8, k = kb + tx;
            if (t < T) g_encT[((size_t)t * B + b) * H + k] = tile[tx][ty + i * 8];
        }
        if (bidx == 0) {
            int tid = ty * 32 + tx;
            for (int i = tid; i < B * H; i += 256) { g_h[i] = 0.0f; g_c[i] = 0.0f; }
            if (tid < B) { g_amax32[tid] = 0u; g_afin[tid] = 0ull; }
        }
    } else {
        int j = bidx - 1792;
        int kb = (j & 31) * 32, jb = (j >> 5) * 32;
#pragma unroll
        for (int i = 0; i < 4; i++)
            tile[ty + i * 8][tx] = W_pred[(size_t)(kb + ty + i * 8) * H + jb + tx];
        __syncthreads();
#pragma unroll
        for (int i = 0; i < 4; i++)
            g_WpT[(size_t)(jb + ty + i * 8) * H + kb + tx] = tile[tx][ty + i * 8];
    }
}

// segments: [0, G*1024) bf16 W_out tiles; [G*1024, +128*1024) Wl; rest: W_out -> [v][k] transpose
__global__ void k_setup2(const float* __restrict__ W_out, const float* __restrict__ Wx,
                         const float* __restrict__ Wh) {
    __shared__ float tile[32][33];
    int bid = blockIdx.x;
    int tid = threadIdx.x;   // 256
    if (bid < G * 1024) {
        int tileI = bid >> 10, k = bid & 1023;
        if (tid < JTILE) {
            int v = tileI * JTILE + tid;
            float val = (v < NV) ? W_out[(size_t)k * NV + v] : 0.0f;
            g_WoutB[((size_t)tileI * 1024 + k) * JTILE + tid] =
                __bfloat16_as_ushort(__float2bfloat16(val));
        }
    } else if (bid < G * 1024 + 128 * 1024) {
        int j = bid - G * 1024;
        int tileI = j >> 10, k = j & 1023;
        if (tid < 64) {
            float val;
            if (tid < 32) val = Wx[(size_t)k * 4096 + (tid >> 3) * 1024 + tileI * 8 + (tid & 7)];
            else { int l2 = tid - 32; val = Wh[(size_t)k * 4096 + (l2 >> 3) * 1024 + tileI * 8 + (l2 & 7)]; }
            g_Wl[((size_t)tileI * 1024 + k) * 64 + tid] = val;
        }
    } else {
        int j = bid - (G * 1024 + 128 * 1024);
        int tile_k = j / 513, tile_v = j - tile_k * 513;
        int kb = tile_k * 32, vb = tile_v * 32;
        int tx = tid & 31, ty = tid >> 5;   // 32 x 8
#pragma unroll
        for (int i = 0; i < 4; i++) {
            int k = kb + ty + i * 8, v = vb + tx;
            tile[ty + i * 8][tx] = (v < NV) ? W_out[(size_t)k * NV + v] : 0.0f;
        }
        __syncthreads();
#pragma unroll
        for (int i = 0; i < 4; i++) {
            int v = vb + ty + i * 8, k = kb + tx;
            g_WoutV[(size_t)v * 1024 + k] = tile[tx][ty + i * 8];
        }
    }
}

__global__ void k_egemm(const float* __restrict__ W_enc, const float* __restrict__ b_joint) {
    __shared__ float xs[B * H];
    int t = blockIdx.y;
    int j = blockIdx.x * 256 + threadIdx.x;
    for (int idx = threadIdx.x; idx < B * H; idx += 256)
        xs[idx] = g_encT[(size_t)t * B * H + idx];
    __syncthreads();
    float acc[B];
#pragma unroll
    for (int b = 0; b < B; b++) acc[b] = 0.0f;
    for (int k = 0; k < H; k += 4) {
        float w0 = __ldg(&W_enc[(size_t)(k + 0) * H + j]);
        float w1 = __ldg(&W_enc[(size_t)(k + 1) * H + j]);
        float w2 = __ldg(&W_enc[(size_t)(k + 2) * H + j]);
        float w3 = __ldg(&W_enc[(size_t)(k + 3) * H + j]);
#pragma unroll
        for (int b = 0; b < B; b++) {
            float4 q4 = *(const float4*)&xs[b * H + k];
            acc[b] = fmaf(q4.x, w0, acc[b]);
            acc[b] = fmaf(q4.y, w1, acc[b]);
            acc[b] = fmaf(q4.z, w2, acc[b]);
            acc[b] = fmaf(q4.w, w3, acc[b]);
        }
    }
    float bj = __ldg(&b_joint[j]);
#pragma unroll
    for (int b = 0; b < B; b++)
        g_E[((size_t)t * B + b) * H + j] = acc[b] + bj;
}

// ---------------- persistent decode kernel ----------------
// smem floats:
//  LSTM : xs[0..8192) hs[8192..16384) wbufs/redu[16384..32768) zs[32768..33024)
//  joint: qs[0..8192) wbufs[8192..22528) redu aliased [8192..24576) logf[24576..25472) spart[25472..25536)
#define SMEM_FLOATS 33024

__global__ void __launch_bounds__(NTHR, 1)
k_decode(const float* __restrict__ emb, const float* __restrict__ bias,
         const float* __restrict__ b_out,
         const int* __restrict__ lens, float* __restrict__ out) {
    extern __shared__ float sm[];
    __shared__ int s_adv[8];
    __shared__ int s_last[8];
    __shared__ float s_gmax[8];
    __shared__ int s_ncand;
    __shared__ int s_cand[128];
    int tid = threadIdx.x, bid = blockIdx.x;
    unsigned smb = (unsigned)__cvta_generic_to_shared(sm);

    for (int s = 0; s < NSTEP; s++) {
        int p = s & 1;
        int is_start = (s == 0);

        // ---- phase D: fp32 re-check of step s-1 candidates ----
        if (s > 0) {
            if (tid < 8) s_gmax[tid] = dec_key32(g_amax32[tid]);
            if (tid == 0) s_ncand = 0;
            __syncthreads();
            const float* logf = sm + 24576;   // persists from joint(s-1)
            for (int o = tid; o < JTILE * 8; o += NTHR) {
                int b = o / JTILE;
                if (logf[o] >= s_gmax[b] - DELTA) {
                    int i = atomicAdd(&s_ncand, 1);
                    if (i < 128) s_cand[i] = (b << 16) | (bid * JTILE + (o - b * JTILE));
                }
            }
            __syncthreads();
            int nc = min(s_ncand, 128);
            int w2 = tid >> 5, ln = tid & 31;
            for (int ci = w2; ci < nc; ci += 16) {
                int pk = s_cand[ci];
                int b = pk >> 16, v = pk & 0xffff;
                const float* wv = g_WoutV + (size_t)v * 1024;
                const float* qv = g_qbj + b * 1024;
                float part = 0.0f;
#pragma unroll 8
                for (int kk = ln; kk < 1024; kk += 32)
                    part = fmaf(wv[kk], qv[kk], part);
#pragma unroll
                for (int off = 16; off > 0; off >>= 1)
                    part += __shfl_down_sync(0xffffffffu, part, off);
                if (ln == 0)
                    atomicMax(&g_afin[b], pack_key(part + __ldg(&b_out[v]), v));
            }
            grid_sync(bid);
        }

        // ---- decisions for step s-1 (read fp32-exact g_afin) ----
        if (tid < 8) {
            int b = tid, advance = 0, lastv = BLANK;
            if (s > 0) {
                int d = s - 1, dp = d & 1;
                unsigned long long key = g_afin[b];
                int sym = BLANK - (int)(unsigned)(key & 0xffffffffu);
                int t = d >> 2, u = d & 3;
                int active = (u == 0) ? (t < lens[b]) : g_advbuf[dp ^ 1][b];
                advance = (active && sym != BLANK) ? 1 : 0;
                int prev_last = (d == 0) ? BLANK : g_lastbuf[dp ^ 1][b];
                lastv = advance ? sym : prev_last;
                g_advbuf[dp][b] = advance;
                g_lastbuf[dp][b] = lastv;
                if (bid == 0)
                    out[(size_t)b * NSTEP + t * MAXSYM + u] = (float)(active ? sym : BLANK);
            }
            s_adv[tid] = advance;
            s_last[tid] = lastv;
        }
        if (bid == 0 && tid >= 32 && tid < 40) g_amax32[tid - 32] = 0u;
        __syncthreads();

        // ---- LSTM (blocks 0..127) ----
        if (bid < 128) {
            const float* h2prev = g_h2[p ^ 1];
            float* xs = sm;
            float* hs = sm + 8192;
#pragma unroll
            for (int bb = 0; bb < 8; bb++) {
                int adv = s_adv[bb];
                const float* hsrc = adv ? (h2prev + bb * H) : (g_h + bb * H);
                const float* xsrc = emb + (size_t)s_last[bb] * H;
                for (int k = tid; k < H; k += NTHR) {
                    float hv = 0.0f, xv = 0.0f;
                    if (!is_start) { hv = hsrc[k]; xv = __ldg(&xsrc[k]); }
                    hs[k * 8 + bb] = hv;
                    xs[k * 8 + bb] = xv;
                }
            }
            __syncthreads();
            if (tid < 64) {
                int idx = bid * 64 + tid;
                int b = idx >> 10, k = idx & 1023;
                g_h[idx] = hs[k * 8 + b];
            }

            {
                int w = tid >> 5, lane = tid & 31;
                int rsub = lane >> 3, jg = lane & 7;
                const float* wtile = g_Wl + ((size_t)bid * 1024 + 64 * w) * 64;
                unsigned bufb = smb + (16384 + w * 1024) * 4;
                const unsigned long long* xu = (const unsigned long long*)xs;
                const unsigned long long* hu = (const unsigned long long*)hs;
                unsigned long long acc[4][4];
#pragma unroll
                for (int c = 0; c < 4; c++)
#pragma unroll
                    for (int bp = 0; bp < 4; bp++) acc[c][bp] = 0ull;

#pragma unroll
                for (int pc = 0; pc < 2; pc++) {
                    const float* src = wtile + (size_t)(8 * pc) * 64;
                    unsigned dst = bufb + pc * 512 * 4;
#pragma unroll
                    for (int i = 0; i < 4; i++)
                        cp16(dst + (lane + 32 * i) * 16, src + (lane + 32 * i) * 4);
                    cp_commit();
                }
#pragma unroll
                for (int ch = 0; ch < 8; ch++) {
                    if (ch == 7) cp_wait0(); else cp_wait1();
                    __syncwarp();
                    int fb = 16384 + w * 1024 + (ch & 1) * 512;
#pragma unroll
                    for (int r = 0; r < 2; r++) {
                        int rr = rsub + 4 * r;
                        int k = 64 * w + 8 * ch + rr;
                        float4 wx4 = *(const float4*)&sm[fb + rr * 64 + jg * 4];
                        float4 wh4 = *(const float4*)&sm[fb + rr * 64 + 32 + jg * 4];
                        unsigned long long wx2[4] = {dup2(wx4.x), dup2(wx4.y), dup2(wx4.z), dup2(wx4.w)};
                        unsigned long long wh2[4] = {dup2(wh4.x), dup2(wh4.y), dup2(wh4.z), dup2(wh4.w)};
#pragma unroll
                        for (int bp = 0; bp < 4; bp++) {
                            unsigned long long xp = xu[k * 4 + bp];
                            unsigned long long hp = hu[k * 4 + bp];
#pragma unroll
                            for (int c = 0; c < 4; c++) {
                                acc[c][bp] = ffma2(xp, wx2[c], acc[c][bp]);
                                acc[c][bp] = ffma2(hp, wh2[c], acc[c][bp]);
                            }
                        }
                    }
                    __syncwarp();
                    if (ch < 6) {
                        const float* src = wtile + (size_t)(8 * (ch + 2)) * 64;
                        unsigned dst = bufb + (ch & 1) * 512 * 4;
#pragma unroll
                        for (int i = 0; i < 4; i++)
                            cp16(dst + (lane + 32 * i) * 16, src + (lane + 32 * i) * 4);
                        cp_commit();
                    }
                }
                __syncthreads();
                unsigned long long* redu = (unsigned long long*)(sm + 16384);
#pragma unroll
                for (int c = 0; c < 4; c++)
#pragma unroll
                    for (int bp = 0; bp < 4; bp++)
                        redu[(c * 4 + bp) * NTHR + tid] = acc[c][bp];
            }
            __syncthreads();
            if (tid < 256) {
                int colIdx = tid >> 3, b = tid & 7;
                int jg = colIdx >> 2, c = colIdx & 3;
                int bp = b >> 1, lane = b & 1;
                const float* redf = sm + 16384;
                float z = 0.0f;
#pragma unroll 8
                for (int kp = 0; kp < 64; kp++)
                    z += redf[((c * 4 + bp) * NTHR + kp * 8 + jg) * 2 + lane];
                int gate = jg >> 1;
                int cc = (jg & 1) * 4 + c;
                z += __ldg(&bias[gate * 1024 + bid * 8 + cc]);
                float* zs = sm + 32768;
                zs[(gate * 8 + cc) * 8 + b] = z;
            }
            __syncthreads();
            if (tid < 64) {
                int b = tid & 7, ch = tid >> 3;
                int jh = bid * 8 + ch;
                const float* zs = sm + 32768;
                float zi = zs[(0 * 8 + ch) * 8 + b];
                float zf = zs[(1 * 8 + ch) * 8 + b];
                float zg = zs[(2 * 8 + ch) * 8 + b];
                float zo = zs[(3 * 8 + ch) * 8 + b];
                float c_eff = 0.0f;
                if (!is_start) c_eff = s_adv[b] ? g_c2[p ^ 1][b * H + jh] : g_c[b * H + jh];
                g_c[b * H + jh] = c_eff;
                float cn = sigm(zf) * c_eff + sigm(zi) * tanhf(zg);
                float hn = sigm(zo) * tanhf(cn);
                g_c2[p][b * H + jh] = cn;
                g_h2[p][b * H + jh] = hn;
            }
        }
        grid_sync(bid);

        // ---- pred (blocks 0..127); block 128 resets g_afin ----
        if (bid < 128) {
            const float* h2c = g_h2[p];
#pragma unroll
            for (int bb = 0; bb < 8; bb++)
                for (int k = tid; k < H; k += NTHR)
                    sm[k * 8 + bb] = h2c[bb * H + k];
            __syncthreads();
            int w = tid >> 5, lane = tid & 31;
            int jloc = w & 7, half = w >> 3;
            int j = bid * 8 + jloc;
            const float4* wp = (const float4*)(g_WpT + (size_t)j * H + half * 512);
            const unsigned long long* hu = (const unsigned long long*)sm;
            unsigned long long acc[4];
#pragma unroll
            for (int bp = 0; bp < 4; bp++) acc[bp] = 0ull;
#pragma unroll
            for (int cIt = 0; cIt < 4; cIt++) {
                int k = half * 512 + cIt * 128 + lane * 4;
                float4 w4 = wp[cIt * 32 + lane];
                unsigned long long w0 = dup2(w4.x), w1 = dup2(w4.y);
                unsigned long long w2 = dup2(w4.z), w3 = dup2(w4.w);
#pragma unroll
                for (int bp = 0; bp < 4; bp++) {
                    acc[bp] = ffma2(hu[(k + 0) * 4 + bp], w0, acc[bp]);
                    acc[bp] = ffma2(hu[(k + 1) * 4 + bp], w1, acc[bp]);
                    acc[bp] = ffma2(hu[(k + 2) * 4 + bp], w2, acc[bp]);
                    acc[bp] = ffma2(hu[(k + 3) * 4 + bp], w3, acc[bp]);
                }
            }
            float a[8];
#pragma unroll
            for (int bp = 0; bp < 4; bp++) {
                unsigned lo, hi;
                asm("mov.b64 {%0, %1}, %2;" : "=r"(lo), "=r"(hi) : "l"(acc[bp]));
                a[bp * 2] = __uint_as_float(lo);
                a[bp * 2 + 1] = __uint_as_float(hi);
            }
#pragma unroll
            for (int off = 16; off > 0; off >>= 1)
#pragma unroll
                for (int b = 0; b < 8; b++)
                    a[b] += __shfl_down_sync(0xffffffffu, a[b], off);
            float* prsh = sm + 8192;
            if (lane == 0) {
#pragma unroll
                for (int b = 0; b < 8; b++)
                    prsh[half * 64 + jloc * 8 + b] = a[b];
            }
            __syncthreads();
            if (tid < 64) {
                int jl = tid >> 3, b = tid & 7;
                int jj = bid * 8 + jl;
                int t = s >> 2;
                float v = prsh[jl * 8 + b] + prsh[64 + jl * 8 + b]
                        + g_E[((size_t)t * B + b) * H + jj];
                float qv = tanhf(v);
                g_qkb[jj * 8 + b] = qv;
                g_qbj[b * 1024 + jj] = qv;
            }
        } else if (bid == 128) {
            if (tid < 8) g_afin[tid] = 0ull;
        }
        grid_sync(bid);

        // ---- joint: bf16 logits = q @ W_outB + b_out, block max ----
        {
            float* qs = sm;
            for (int i = tid; i < H * B; i += NTHR) qs[i] = g_qkb[i];
            __syncthreads();
            const unsigned long long* qu = (const unsigned long long*)qs;
            int w = tid >> 5, vg = tid & 31;
            int vgc = (vg < 28) ? vg : 27;
            const unsigned short* wtile = g_WoutB + ((size_t)bid * 1024 + 64 * w) * JTILE;
            unsigned bufb = smb + (8192 + w * 896) * 4;
            unsigned long long acc[4][4];
#pragma unroll
            for (int c = 0; c < 4; c++)
#pragma unroll
                for (int bp = 0; bp < 4; bp++) acc[c][bp] = 0ull;

#pragma unroll
            for (int pc = 0; pc < 2; pc++) {
                const unsigned short* src = wtile + (size_t)(8 * pc) * JTILE;
                unsigned dst = bufb + pc * 1792;
#pragma unroll
                for (int i = 0; i < 4; i++) {
                    int idx = vg + 32 * i;
                    if (idx < 112) cp16(dst + idx * 16, src + idx * 8);
                }
                cp_commit();
            }
#pragma unroll
            for (int ch = 0; ch < 8; ch++) {
                if (ch == 7) cp_wait0(); else cp_wait1();
                __syncwarp();
                const uint2* wrow = (const uint2*)(sm + 8192 + w * 896 + (ch & 1) * 448);
#pragma unroll
                for (int rr = 0; rr < 8; rr++) {
                    int k = 64 * w + 8 * ch + rr;
                    uint2 aw = wrow[rr * 28 + vgc];
                    unsigned long long w0 = dup2lo(aw.x), w1 = dup2hi(aw.x);
                    unsigned long long w2 = dup2lo(aw.y), w3 = dup2hi(aw.y);
#pragma unroll
                    for (int bp = 0; bp < 4; bp++) {
                        unsigned long long qp = qu[k * 4 + bp];
                        acc[0][bp] = ffma2(qp, w0, acc[0][bp]);
                        acc[1][bp] = ffma2(qp, w1, acc[1][bp]);
                        acc[2][bp] = ffma2(qp, w2, acc[2][bp]);
                        acc[3][bp] = ffma2(qp, w3, acc[3][bp]);
                    }
                }
                __syncwarp();
                if (ch < 6) {
                    const unsigned short* src = wtile + (size_t)(8 * (ch + 2)) * JTILE;
                    unsigned dst = bufb + (ch & 1) * 1792;
#pragma unroll
                    for (int i = 0; i < 4; i++) {
                        int idx = vg + 32 * i;
                        if (idx < 112) cp16(dst + idx * 16, src + idx * 8);
                    }
                    cp_commit();
                }
            }
            __syncthreads();
            unsigned long long* redu = (unsigned long long*)(sm + 8192);
            const float* redf = sm + 8192;
#pragma unroll
            for (int c = 0; c < 4; c++)
#pragma unroll
                for (int bp = 0; bp < 4; bp++)
                    redu[(c * 4 + bp) * NTHR + tid] = acc[c][bp];
            __syncthreads();
            float* logf = sm + 24576;
            for (int o = tid; o < JTILE * 8; o += NTHR) {
                int b = o / JTILE, col = o - b * JTILE;
                int vg2 = col >> 2, c = col & 3, bp = b >> 1, lane = b & 1;
                float sv = 0.0f;
#pragma unroll
                for (int kc2 = 0; kc2 < 16; kc2++)
                    sv += redf[((c * 4 + bp) * NTHR + kc2 * 32 + vg2) * 2 + lane];
                int v = bid * JTILE + col;
                logf[o] = (v < NV) ? sv + __ldg(&b_out[v]) : -1e30f;
            }
            __syncthreads();
            float* spart = sm + 24576 + 896;
            if (tid < 64) {
                int b = tid >> 3, part = tid & 7;
                float m = -1e30f;
#pragma unroll
                for (int cc = 0; cc < 14; cc++)
                    m = fmaxf(m, logf[b * JTILE + part * 14 + cc]);
                spart[tid] = m;
            }
            __syncthreads();
            if (tid < 8) {
                float m = -1e30f;
#pragma unroll
                for (int pp = 0; pp < 8; pp++) m = fmaxf(m, spart[tid * 8 + pp]);
                atomicMax(&g_amax32[tid], enc32(m));
            }
        }
        grid_sync(bid);
    }

    // ---- epilogue: phase D for d = NSTEP-1, final decision + h,c output ----
    {
        if (tid < 8) s_gmax[tid] = dec_key32(g_amax32[tid]);
        if (tid == 0) s_ncand = 0;
        __syncthreads();
        const float* logf = sm + 24576;
        for (int o = tid; o < JTILE * 8; o += NTHR) {
            int b = o / JTILE;
            if (logf[o] >= s_gmax[b] - DELTA) {
                int i = atomicAdd(&s_ncand, 1);
                if (i < 128) s_cand[i] = (b << 16) | (bid * JTILE + (o - b * JTILE));
            }
        }
        __syncthreads();
        int nc = min(s_ncand, 128);
        int w2 = tid >> 5, ln = tid & 31;
        for (int ci = w2; ci < nc; ci += 16) {
            int pk = s_cand[ci];
            int b = pk >> 16, v = pk & 0xffff;
            const float* wv = g_WoutV + (size_t)v * 1024;
            const float* qv = g_qbj + b * 1024;
            float part = 0.0f;
#pragma unroll 8
            for (int kk = ln; kk < 1024; kk += 32)
                part = fmaf(wv[kk], qv[kk], part);
#pragma unroll
            for (int off = 16; off > 0; off >>= 1)
                part += __shfl_down_sync(0xffffffffu, part, off);
            if (ln == 0)
                atomicMax(&g_afin[b], pack_key(part + __ldg(&b_out[v]), v));
        }
        grid_sync(bid);

        int d = NSTEP - 1, dp = d & 1;
        if (tid < 8) {
            int b = tid;
            unsigned long long key = g_afin[b];
            int sym = BLANK - (int)(unsigned)(key & 0xffffffffu);
            int t = d >> 2, u = d & 3;
            int active = (u == 0) ? (t < lens[b]) : g_advbuf[dp ^ 1][b];
            int advance = (active && sym != BLANK) ? 1 : 0;
            if (bid == 0)
                out[(size_t)b * NSTEP + t * MAXSYM + u] = (float)(active ? sym : BLANK);
            s_adv[tid] = advance;
        }
        __syncthreads();
        for (int i = bid * NTHR + tid; i < B * H; i += G * NTHR) {
            int b = i >> 10;
            float hf = s_adv[b] ? g_h2[dp][i] : g_h[i];
            float cf = s_adv[b] ? g_c2[dp][i] : g_c[i];
            out[B * NSTEP + i] = hf;
            out[B * NSTEP + B * H + i] = cf;
        }
    }
}

extern "C" void kernel_launch(void* const* d_in, const int* in_sizes, int n_in,
                              void* d_out, int out_size) {
    (void)in_sizes; (void)n_in; (void)out_size;
    const float* enc     = (const float*)d_in[0];
    const int*   lens    = (const int*)d_in[1];
    const float* emb     = (const float*)d_in[2];
    const float* Wx      = (const float*)d_in[3];
    const float* Wh      = (const float*)d_in[4];
    const float* bias    = (const float*)d_in[5];
    const float* W_enc   = (const float*)d_in[6];
    const float* W_pred  = (const float*)d_in[7];
    const float* b_joint = (const float*)d_in[8];
    const float* W_out   = (const float*)d_in[9];
    const float* b_out   = (const float*)d_in[10];
    float* out = (float*)d_out;

    static int configured = 0;
    if (!configured) {
        cudaFuncSetAttribute(k_decode, cudaFuncAttributeMaxDynamicSharedMemorySize,
                             SMEM_FLOATS * 4);
        configured = 1;
    }

    k_setup1<<<2816, dim3(32, 8)>>>(enc, W_pred);
    k_setup2<<<G * 1024 + 128 * 1024 + 513 * 32, 256>>>(W_out, Wx, Wh);
    k_egemm<<<dim3(4, T), 256>>>(W_enc, b_joint);
    k_decode<<<G, NTHR, SMEM_FLOATS * 4>>>(emb, bias, b_out, lens, out);
}

// round 8
// speedup vs baseline: 1.1923x; 1.1923x over previous
#include <cuda_runtime.h>
#include <cuda_bf16.h>
#include <math.h>

// RNN-T greedy decode, persistent kernel, 1024 thr/block (occ 50%).
// LSTM/pred fp32; joint bf16 + exact fp32 re-check.
#define B 8
#define T 200
#define H 1024
#define NV 16385
#define BLANK 16384
#define MAXSYM 4
#define NSTEP (T * MAXSYM) // 800
#define G 148
#define NTHR 1024
#define JTILE 112          // vocab cols per block in joint (148*112 = 16576 >= NV)
#define DELTA 0.0625f

// ---------------- device scratch ----------------
__device__ __align__(16) float g_encT[T * B * H];
__device__ __align__(16) float g_E[T * B * H];
__device__ __align__(16) unsigned short g_WoutB[(size_t)G * 1024 * JTILE + 64]; // bf16 [tile][k][112]
__device__ __align__(16) float g_WoutV[(size_t)16416 * 1024];                   // fp32 [v][k]
__device__ __align__(16) float g_Wl[(size_t)128 * 1024 * 64 + 128];             // [tile][k][wx32|wh32]
__device__ __align__(16) float g_WpT[H * H];                                    // [j][k]
__device__ float g_h[B * H];
__device__ float g_c[B * H];
__device__ float g_h2[2][B * H];
__device__ float g_c2[2][B * H];
__device__ float g_qkb[H * B];     // q in [j][b]
__device__ float g_qbj[B * H];     // q in [b][j]
__device__ int   g_lastbuf[2][B];
__device__ int   g_advbuf[2][B];
__device__ unsigned g_amax32[B];
__device__ unsigned long long g_afin[B];
__device__ unsigned g_leaf[8];
__device__ unsigned g_root;
__device__ unsigned g_gen;

// ---------------- helpers ----------------
__device__ __forceinline__ unsigned long long ffma2(unsigned long long a,
                                                    unsigned long long b,
                                                    unsigned long long c) {
    unsigned long long d;
    asm("fma.rn.f32x2 %0, %1, %2, %3;" : "=l"(d) : "l"(a), "l"(b), "l"(c));
    return d;
}
__device__ __forceinline__ unsigned long long dup2(float w) {
    unsigned long long r;
    unsigned u = __float_as_uint(w);
    asm("mov.b64 %0, {%1, %1};" : "=l"(r) : "r"(u));
    return r;
}
__device__ __forceinline__ unsigned long long dup2lo(unsigned a) {
    unsigned f = a << 16; unsigned long long r;
    asm("mov.b64 %0, {%1, %1};" : "=l"(r) : "r"(f));
    return r;
}
__device__ __forceinline__ unsigned long long dup2hi(unsigned a) {
    unsigned f = a & 0xFFFF0000u; unsigned long long r;
    asm("mov.b64 %0, {%1, %1};" : "=l"(r) : "r"(f));
    return r;
}
__device__ __forceinline__ unsigned long long pack_key(float f, int v) {
    unsigned u = __float_as_uint(f);
    u = (u & 0x80000000u) ? ~u : (u | 0x80000000u);
    return ((unsigned long long)u << 32) | (unsigned)(BLANK - v);
}
__device__ __forceinline__ unsigned enc32(float f) {
    unsigned u = __float_as_uint(f);
    return (u & 0x80000000u) ? ~u : (u | 0x80000000u);
}
__device__ __forceinline__ float dec_key32(unsigned e) {
    unsigned u = (e & 0x80000000u) ? (e ^ 0x80000000u) : ~e;
    return __uint_as_float(u);
}
__device__ __forceinline__ float sigm(float x) { return 1.0f / (1.0f + expf(-x)); }

__device__ __forceinline__ void grid_sync(int bid) {
    __syncthreads();
    if (threadIdx.x == 0) {
        __threadfence();
        unsigned gen = *(volatile unsigned*)&g_gen;
        int leaf = bid & 7;
        unsigned cnt = (leaf < 4) ? 19u : 18u;
        unsigned t = atomicAdd(&g_leaf[leaf], 1u);
        if ((t % cnt) == cnt - 1u) {
            unsigned rt = atomicAdd(&g_root, 1u);
            if ((rt & 7u) == 7u) {
                __threadfence();
                atomicExch(&g_gen, gen + 1u);
            }
        }
        while (*(volatile unsigned*)&g_gen == gen) {}
        __threadfence();
    }
    __syncthreads();
}

// ---------------- setup kernels (unchanged packs) ----------------
__global__ void k_setup1(const float* __restrict__ enc, const float* __restrict__ W_pred) {
    __shared__ float tile[32][33];
    int bidx = blockIdx.x;
    int tx = threadIdx.x, ty = threadIdx.y;   // 32 x 8
    if (bidx < 1792) {
        int b = bidx & 7, kb = ((bidx >> 3) & 31) * 32, tb = (bidx >> 8) * 32;
#pragma unroll
        for (int i = 0; i < 4; i++) {
            int k = kb + ty + i * 8, t = tb + tx;
            tile[ty + i * 8][tx] = (t < T) ? enc[(size_t)b * H * T + (size_t)k * T + t] : 0.0f;
        }
        __syncthreads();
#pragma unroll
        for (int i = 0; i < 4; i++) {
            int t = tb + ty + i * 8, k = kb + tx;
            if (t < T) g_encT[((size_t)t * B + b) * H + k] = tile[tx][ty + i * 8];
        }
        if (bidx == 0) {
            int tid = ty * 32 + tx;
            for (int i = tid; i < B * H; i += 256) { g_h[i] = 0.0f; g_c[i] = 0.0f; }
            if (tid < B) { g_amax32[tid] = 0u; g_afin[tid] = 0ull; }
        }
    } else {
        int j = bidx - 1792;
        int kb = (j & 31) * 32, jb = (j >> 5) * 32;
#pragma unroll
        for (int i = 0; i < 4; i++)
            tile[ty + i * 8][tx] = W_pred[(size_t)(kb + ty + i * 8) * H + jb + tx];
        __syncthreads();
#pragma unroll
        for (int i = 0; i < 4; i++)
            g_WpT[(size_t)(jb + ty + i * 8) * H + kb + tx] = tile[tx][ty + i * 8];
    }
}

__global__ void k_setup2(const float* __restrict__ W_out, const float* __restrict__ Wx,
                         const float* __restrict__ Wh) {
    __shared__ float tile[32][33];
    int bid = blockIdx.x;
    int tid = threadIdx.x;   // 256
    if (bid < G * 1024) {
        int tileI = bid >> 10, k = bid & 1023;
        if (tid < JTILE) {
            int v = tileI * JTILE + tid;
            float val = (v < NV) ? W_out[(size_t)k * NV + v] : 0.0f;
            g_WoutB[((size_t)tileI * 1024 + k) * JTILE + tid] =
                __bfloat16_as_ushort(__float2bfloat16(val));
        }
    } else if (bid < G * 1024 + 128 * 1024) {
        int j = bid - G * 1024;
        int tileI = j >> 10, k = j & 1023;
        if (tid < 64) {
            float val;
            if (tid < 32) val = Wx[(size_t)k * 4096 + (tid >> 3) * 1024 + tileI * 8 + (tid & 7)];
            else { int l2 = tid - 32; val = Wh[(size_t)k * 4096 + (l2 >> 3) * 1024 + tileI * 8 + (l2 & 7)]; }
            g_Wl[((size_t)tileI * 1024 + k) * 64 + tid] = val;
        }
    } else {
        int j = bid - (G * 1024 + 128 * 1024);
        int tile_k = j / 513, tile_v = j - tile_k * 513;
        int kb = tile_k * 32, vb = tile_v * 32;
        int tx = tid & 31, ty = tid >> 5;   // 32 x 8
#pragma unroll
        for (int i = 0; i < 4; i++) {
            int k = kb + ty + i * 8, v = vb + tx;
            tile[ty + i * 8][tx] = (v < NV) ? W_out[(size_t)k * NV + v] : 0.0f;
        }
        __syncthreads();
#pragma unroll
        for (int i = 0; i < 4; i++) {
            int v = vb + ty + i * 8, k = kb + tx;
            g_WoutV[(size_t)v * 1024 + k] = tile[tx][ty + i * 8];
        }
    }
}

__global__ void k_egemm(const float* __restrict__ W_enc, const float* __restrict__ b_joint) {
    __shared__ float xs[B * H];
    int t = blockIdx.y;
    int j = blockIdx.x * 256 + threadIdx.x;
    for (int idx = threadIdx.x; idx < B * H; idx += 256)
        xs[idx] = g_encT[(size_t)t * B * H + idx];
    __syncthreads();
    float acc[B];
#pragma unroll
    for (int b = 0; b < B; b++) acc[b] = 0.0f;
    for (int k = 0; k < H; k += 4) {
        float w0 = __ldg(&W_enc[(size_t)(k + 0) * H + j]);
        float w1 = __ldg(&W_enc[(size_t)(k + 1) * H + j]);
        float w2 = __ldg(&W_enc[(size_t)(k + 2) * H + j]);
        float w3 = __ldg(&W_enc[(size_t)(k + 3) * H + j]);
#pragma unroll
        for (int b = 0; b < B; b++) {
            float4 q4 = *(const float4*)&xs[b * H + k];
            acc[b] = fmaf(q4.x, w0, acc[b]);
            acc[b] = fmaf(q4.y, w1, acc[b]);
            acc[b] = fmaf(q4.z, w2, acc[b]);
            acc[b] = fmaf(q4.w, w3, acc[b]);
        }
    }
    float bj = __ldg(&b_joint[j]);
#pragma unroll
    for (int b = 0; b < B; b++)
        g_E[((size_t)t * B + b) * H + j] = acc[b] + bj;
}

// ---------------- persistent decode kernel ----------------
// smem floats:
//  A [0,8192): xs (LSTM) / h2 stage (pred) / qs (joint)
//  B [8192,16384): hs (LSTM) / prsh (pred)
//  C [16384,32768): redu (8 acc64 x 1024 thr = 64 KB) (LSTM, joint)
//  D [32768,33024): zs (LSTM)
//  E [33024,33920): logf (joint -> phase D)  [33920,33984): spart
#define SMEM_FLOATS 33984

__global__ void __launch_bounds__(NTHR, 1)
k_decode(const float* __restrict__ emb, const float* __restrict__ bias,
         const float* __restrict__ b_out,
         const int* __restrict__ lens, float* __restrict__ out) {
    extern __shared__ float sm[];
    __shared__ int s_adv[8];
    __shared__ int s_last[8];
    __shared__ float s_gmax[8];
    __shared__ int s_ncand;
    __shared__ int s_cand[128];
    int tid = threadIdx.x, bid = blockIdx.x;

    for (int s = 0; s < NSTEP; s++) {
        int p = s & 1;
        int is_start = (s == 0);

        // ---- phase D: fp32 re-check of step s-1 candidates ----
        if (s > 0) {
            if (tid < 8) s_gmax[tid] = dec_key32(g_amax32[tid]);
            if (tid == 0) s_ncand = 0;
            __syncthreads();
            const float* logf = sm + 33024;
            for (int o = tid; o < JTILE * 8; o += NTHR) {
                int b = o / JTILE;
                if (logf[o] >= s_gmax[b] - DELTA) {
                    int i = atomicAdd(&s_ncand, 1);
                    if (i < 128) s_cand[i] = (b << 16) | (bid * JTILE + (o - b * JTILE));
                }
            }
            __syncthreads();
            int nc = min(s_ncand, 128);
            int w2 = tid >> 5, ln = tid & 31;
            for (int ci = w2; ci < nc; ci += 32) {
                int pk = s_cand[ci];
                int b = pk >> 16, v = pk & 0xffff;
                const float* wv = g_WoutV + (size_t)v * 1024;
                const float* qv = g_qbj + b * 1024;
                float part = 0.0f;
#pragma unroll 8
                for (int kk = ln; kk < 1024; kk += 32)
                    part = fmaf(wv[kk], qv[kk], part);
#pragma unroll
                for (int off = 16; off > 0; off >>= 1)
                    part += __shfl_down_sync(0xffffffffu, part, off);
                if (ln == 0)
                    atomicMax(&g_afin[b], pack_key(part + __ldg(&b_out[v]), v));
            }
            grid_sync(bid);
        }

        // ---- decisions for step s-1 ----
        if (tid < 8) {
            int b = tid, advance = 0, lastv = BLANK;
            if (s > 0) {
                int d = s - 1, dp = d & 1;
                unsigned long long key = g_afin[b];
                int sym = BLANK - (int)(unsigned)(key & 0xffffffffu);
                int t = d >> 2, u = d & 3;
                int active = (u == 0) ? (t < lens[b]) : g_advbuf[dp ^ 1][b];
                advance = (active && sym != BLANK) ? 1 : 0;
                int prev_last = (d == 0) ? BLANK : g_lastbuf[dp ^ 1][b];
                lastv = advance ? sym : prev_last;
                g_advbuf[dp][b] = advance;
                g_lastbuf[dp][b] = lastv;
                if (bid == 0)
                    out[(size_t)b * NSTEP + t * MAXSYM + u] = (float)(active ? sym : BLANK);
            }
            s_adv[tid] = advance;
            s_last[tid] = lastv;
        }
        if (bid == 0 && tid >= 32 && tid < 40) g_amax32[tid - 32] = 0u;
        __syncthreads();

        // ---- LSTM (blocks 0..127, 8 hidden cols each) ----
        if (bid < 128) {
            const float* h2prev = g_h2[p ^ 1];
            float* xs = sm;
            float* hs = sm + 8192;
#pragma unroll
            for (int bb = 0; bb < 8; bb++) {
                int adv = s_adv[bb];
                const float* hsrc = adv ? (h2prev + bb * H) : (g_h + bb * H);
                const float* xsrc = emb + (size_t)s_last[bb] * H;
                int k = tid;   // 1024 threads cover all k in one pass
                float hv = 0.0f, xv = 0.0f;
                if (!is_start) { hv = hsrc[k]; xv = __ldg(&xsrc[k]); }
                hs[k * 8 + bb] = hv;
                xs[k * 8 + bb] = xv;
            }
            __syncthreads();
            if (tid < 64) {   // commit h
                int idx = bid * 64 + tid;
                int b = idx >> 10, k = idx & 1023;
                g_h[idx] = hs[k * 8 + b];
            }

            {
                int kp = tid >> 5;        // 32 k-chunks of 32
                int jg = tid & 31;        // covers gate-col pair l = jg*2, jg*2+1 (jg<16 wx, >=16 wh)
                const float* wt = g_Wl + ((size_t)bid * 1024) * 64;
                const unsigned long long* xh =
                    (jg < 16) ? (const unsigned long long*)xs : (const unsigned long long*)hs;
                unsigned long long acc[2][4];
#pragma unroll
                for (int c = 0; c < 2; c++)
#pragma unroll
                    for (int bp = 0; bp < 4; bp++) acc[c][bp] = 0ull;
                int k0 = kp * 32;
                float2 cur = *(const float2*)&wt[(size_t)k0 * 64 + jg * 2];
                float2 nxt = *(const float2*)&wt[(size_t)(k0 + 1) * 64 + jg * 2];
#pragma unroll 4
                for (int k = k0; k < k0 + 32; k++) {
                    float2 w = cur; cur = nxt;
                    nxt = *(const float2*)&wt[(size_t)(k + 2) * 64 + jg * 2];
                    unsigned long long w0 = dup2(w.x), w1 = dup2(w.y);
#pragma unroll
                    for (int bp = 0; bp < 4; bp++) {
                        unsigned long long xp = xh[k * 4 + bp];
                        acc[0][bp] = ffma2(xp, w0, acc[0][bp]);
                        acc[1][bp] = ffma2(xp, w1, acc[1][bp]);
                    }
                }
                unsigned long long* redu = (unsigned long long*)(sm + 16384);
#pragma unroll
                for (int c = 0; c < 2; c++)
#pragma unroll
                    for (int bp = 0; bp < 4; bp++)
                        redu[(c * 4 + bp) * NTHR + tid] = acc[c][bp];
            }
            __syncthreads();
            if (tid < 256) {   // 32 gate-cols x 8 b
                int gc = tid >> 3, b = tid & 7;
                int jgx = gc >> 1, cc = gc & 1;
                int bp = b >> 1, half = b & 1;
                const float* redf = sm + 16384;
                float z = 0.0f;
#pragma unroll 8
                for (int kp = 0; kp < 32; kp++) {
                    z += redf[((cc * 4 + bp) * NTHR + kp * 32 + jgx) * 2 + half];
                    z += redf[((cc * 4 + bp) * NTHR + kp * 32 + 16 + jgx) * 2 + half];
                }
                int gate = gc >> 3, ch = gc & 7;
                z += __ldg(&bias[gate * 1024 + bid * 8 + ch]);
                float* zs = sm + 32768;
                zs[gc * 8 + b] = z;
            }
            __syncthreads();
            if (tid < 64) {
                int b = tid & 7, ch = tid >> 3;
                int jh = bid * 8 + ch;
                const float* zs = sm + 32768;
                float zi = zs[(0 * 8 + ch) * 8 + b];
                float zf = zs[(1 * 8 + ch) * 8 + b];
                float zg = zs[(2 * 8 + ch) * 8 + b];
                float zo = zs[(3 * 8 + ch) * 8 + b];
                float c_eff = 0.0f;
                if (!is_start) c_eff = s_adv[b] ? g_c2[p ^ 1][b * H + jh] : g_c[b * H + jh];
                g_c[b * H + jh] = c_eff;
                float cn = sigm(zf) * c_eff + sigm(zi) * tanhf(zg);
                float hn = sigm(zo) * tanhf(cn);
                g_c2[p][b * H + jh] = cn;
                g_h2[p][b * H + jh] = hn;
            }
        }
        grid_sync(bid);

        // ---- pred (blocks 0..127, 8 j each); block 128 resets g_afin ----
        if (bid < 128) {
            const float* h2c = g_h2[p];
#pragma unroll
            for (int bb = 0; bb < 8; bb++) {
                int k = tid;
                sm[k * 8 + bb] = h2c[bb * H + k];
            }
            __syncthreads();
            int w = tid >> 5, lane = tid & 31;
            int jloc = w & 7, q4 = w >> 3;       // 8 j x 4 k-quarters
            int j = bid * 8 + jloc;
            const float4* wp = (const float4*)(g_WpT + (size_t)j * H + q4 * 256);
            const unsigned long long* hu = (const unsigned long long*)sm;
            unsigned long long acc[4];
#pragma unroll
            for (int bp = 0; bp < 4; bp++) acc[bp] = 0ull;
#pragma unroll
            for (int cIt = 0; cIt < 2; cIt++) {
                int k = q4 * 256 + cIt * 128 + lane * 4;
                float4 w4 = wp[cIt * 32 + lane];
                unsigned long long w0 = dup2(w4.x), w1 = dup2(w4.y);
                unsigned long long w2 = dup2(w4.z), w3 = dup2(w4.w);
#pragma unroll
                for (int bp = 0; bp < 4; bp++) {
                    acc[bp] = ffma2(hu[(k + 0) * 4 + bp], w0, acc[bp]);
                    acc[bp] = ffma2(hu[(k + 1) * 4 + bp], w1, acc[bp]);
                    acc[bp] = ffma2(hu[(k + 2) * 4 + bp], w2, acc[bp]);
                    acc[bp] = ffma2(hu[(k + 3) * 4 + bp], w3, acc[bp]);
                }
            }
            float a[8];
#pragma unroll
            for (int bp = 0; bp < 4; bp++) {
                unsigned lo, hi;
                asm("mov.b64 {%0, %1}, %2;" : "=r"(lo), "=r"(hi) : "l"(acc[bp]));
                a[bp * 2] = __uint_as_float(lo);
                a[bp * 2 + 1] = __uint_as_float(hi);
            }
#pragma unroll
            for (int off = 16; off > 0; off >>= 1)
#pragma unroll
                for (int b = 0; b < 8; b++)
                    a[b] += __shfl_down_sync(0xffffffffu, a[b], off);
            float* prsh = sm + 8192;   // [q4][jloc][b] = 256 floats
            if (lane == 0) {
#pragma unroll
                for (int b = 0; b < 8; b++)
                    prsh[q4 * 64 + jloc * 8 + b] = a[b];
            }
            __syncthreads();
            if (tid < 64) {
                int jl = tid >> 3, b = tid & 7;
                int jj = bid * 8 + jl;
                int t = s >> 2;
                float v = prsh[jl * 8 + b] + prsh[64 + jl * 8 + b]
                        + prsh[128 + jl * 8 + b] + prsh[192 + jl * 8 + b]
                        + g_E[((size_t)t * B + b) * H + jj];
                float qv = tanhf(v);
                g_qkb[jj * 8 + b] = qv;
                g_qbj[b * 1024 + jj] = qv;
            }
        } else if (bid == 128) {
            if (tid < 8) g_afin[tid] = 0ull;
        }
        grid_sync(bid);

        // ---- joint: bf16 logits = q @ W_outB + b_out, block max (148 blocks, 112 cols) ----
        {
            float* qs = sm;
            for (int i = tid; i < H * B; i += NTHR) qs[i] = g_qkb[i];
            __syncthreads();
            const unsigned long long* qu = (const unsigned long long*)qs;
            int kc = tid >> 6;        // 16 k-chunks of 64
            int vg = tid & 63;        // <56 active: cols vg*2, vg*2+1
            unsigned long long acc[2][4];
#pragma unroll
            for (int c = 0; c < 2; c++)
#pragma unroll
                for (int bp = 0; bp < 4; bp++) acc[c][bp] = 0ull;
            if (vg < 56) {
                const unsigned short* wt = g_WoutB + ((size_t)bid * 1024) * JTILE + vg * 2;
                int k0 = kc * 64;
                unsigned cur = *(const unsigned*)&wt[(size_t)k0 * JTILE];
                unsigned nxt = *(const unsigned*)&wt[(size_t)(k0 + 1) * JTILE];
#pragma unroll 4
                for (int k = k0; k < k0 + 64; k++) {
                    unsigned wv = cur; cur = nxt;
                    nxt = *(const unsigned*)&wt[(size_t)(k + 2) * JTILE];
                    unsigned long long w0 = dup2lo(wv), w1 = dup2hi(wv);
#pragma unroll
                    for (int bp = 0; bp < 4; bp++) {
                        unsigned long long qp = qu[k * 4 + bp];
                        acc[0][bp] = ffma2(qp, w0, acc[0][bp]);
                        acc[1][bp] = ffma2(qp, w1, acc[1][bp]);
                    }
                }
            }
            unsigned long long* redu = (unsigned long long*)(sm + 16384);
            const float* redf = sm + 16384;
#pragma unroll
            for (int c = 0; c < 2; c++)
#pragma unroll
                for (int bp = 0; bp < 4; bp++)
                    redu[(c * 4 + bp) * NTHR + tid] = acc[c][bp];
            __syncthreads();
            float* logf = sm + 33024;
            for (int o = tid; o < JTILE * 8; o += NTHR) {
                int b = o / JTILE, col = o - b * JTILE;
                int vg2 = col >> 1, cc = col & 1, bp = b >> 1, half = b & 1;
                float sv = 0.0f;
#pragma unroll
                for (int kc2 = 0; kc2 < 16; kc2++)
                    sv += redf[((cc * 4 + bp) * NTHR + kc2 * 64 + vg2) * 2 + half];
                int v = bid * JTILE + col;
                logf[o] = (v < NV) ? sv + __ldg(&b_out[v]) : -1e30f;
            }
            __syncthreads();
            float* spart = sm + 33920;
            if (tid < 64) {
                int b = tid >> 3, part = tid & 7;
                float m = -1e30f;
#pragma unroll
                for (int cc = 0; cc < 14; cc++)
                    m = fmaxf(m, logf[b * JTILE + part * 14 + cc]);
                spart[tid] = m;
            }
            __syncthreads();
            if (tid < 8) {
                float m = -1e30f;
#pragma unroll
                for (int pp = 0; pp < 8; pp++) m = fmaxf(m, spart[tid * 8 + pp]);
                atomicMax(&g_amax32[tid], enc32(m));
            }
        }
        grid_sync(bid);
    }

    // ---- epilogue: phase D for d = NSTEP-1, final decision + h,c output ----
    {
        if (tid < 8) s_gmax[tid] = dec_key32(g_amax32[tid]);
        if (tid == 0) s_ncand = 0;
        __syncthreads();
        const float* logf = sm + 33024;
        for (int o = tid; o < JTILE * 8; o += NTHR) {
            int b = o / JTILE;
            if (logf[o] >= s_gmax[b] - DELTA) {
                int i = atomicAdd(&s_ncand, 1);
                if (i < 128) s_cand[i] = (b << 16) | (bid * JTILE + (o - b * JTILE));
            }
        }
        __syncthreads();
        int nc = min(s_ncand, 128);
        int w2 = tid >> 5, ln = tid & 31;
        for (int ci = w2; ci < nc; ci += 32) {
            int pk = s_cand[ci];
            int b = pk >> 16, v = pk & 0xffff;
            const float* wv = g_WoutV + (size_t)v * 1024;
            const float* qv = g_qbj + b * 1024;
            float part = 0.0f;
#pragma unroll 8
            for (int kk = ln; kk < 1024; kk += 32)
                part = fmaf(wv[kk], qv[kk], part);
#pragma unroll
            for (int off = 16; off > 0; off >>= 1)
                part += __shfl_down_sync(0xffffffffu, part, off);
            if (ln == 0)
                atomicMax(&g_afin[b], pack_key(part + __ldg(&b_out[v]), v));
        }
        grid_sync(bid);

        int d = NSTEP - 1, dp = d & 1;
        if (tid < 8) {
            int b = tid;
            unsigned long long key = g_afin[b];
            int sym = BLANK - (int)(unsigned)(key & 0xffffffffu);
            int t = d >> 2, u = d & 3;
            int active = (u == 0) ? (t < lens[b]) : g_advbuf[dp ^ 1][b];
            int advance = (active && sym != BLANK) ? 1 : 0;
            if (bid == 0)
                out[(size_t)b * NSTEP + t * MAXSYM + u] = (float)(active ? sym : BLANK);
            s_adv[tid] = advance;
        }
        __syncthreads();
        for (int i = bid * NTHR + tid; i < B * H; i += G * NTHR) {
            int b = i >> 10;
            float hf = s_adv[b] ? g_h2[dp][i] : g_h[i];
            float cf = s_adv[b] ? g_c2[dp][i] : g_c[i];
            out[B * NSTEP + i] = hf;
            out[B * NSTEP + B * H + i] = cf;
        }
    }
}

extern "C" void kernel_launch(void* const* d_in, const int* in_sizes, int n_in,
                              void* d_out, int out_size) {
    (void)in_sizes; (void)n_in; (void)out_size;
    const float* enc     = (const float*)d_in[0];
    const int*   lens    = (const int*)d_in[1];
    const float* emb     = (const float*)d_in[2];
    const float* Wx      = (const float*)d_in[3];
    const float* Wh      = (const float*)d_in[4];
    const float* bias    = (const float*)d_in[5];
    const float* W_enc   = (const float*)d_in[6];
    const float* W_pred  = (const float*)d_in[7];
    const float* b_joint = (const float*)d_in[8];
    const float* W_out   = (const float*)d_in[9];
    const float* b_out   = (const float*)d_in[10];
    float* out = (float*)d_out;

    static int configured = 0;
    if (!configured) {
        cudaFuncSetAttribute(k_decode, cudaFuncAttributeMaxDynamicSharedMemorySize,
                             SMEM_FLOATS * 4);
        configured = 1;
    }

    k_setup1<<<2816, dim3(32, 8)>>>(enc, W_pred);
    k_setup2<<<G * 1024 + 128 * 1024 + 513 * 32, 256>>>(W_out, Wx, Wh);
    k_egemm<<<dim3(4, T), 256>>>(W_enc, b_joint);
    k_decode<<<G, NTHR, SMEM_FLOATS * 4>>>(emb, bias, b_out, lens, out);
}

// round 9
// speedup vs baseline: 1.2979x; 1.0885x over previous
#include <cuda_runtime.h>
#include <cuda_bf16.h>
#include <math.h>

// RNN-T greedy decode, persistent kernel, 1024 thr/block.
// LSTM/pred fp32; joint bf16 with in-phase exact fp32 re-check (block-local threshold).
#define B 8
#define T 200
#define H 1024
#define NV 16385
#define BLANK 16384
#define MAXSYM 4
#define NSTEP (T * MAXSYM) // 800
#define G 148
#define NTHR 1024
#define JTILE 112          // vocab cols per block in joint (148*112 = 16576 >= NV)
#define DELTA 0.0625f

// ---------------- device scratch ----------------
__device__ __align__(16) float g_encT[T * B * H];
__device__ __align__(16) float g_E[T * B * H];
__device__ __align__(16) unsigned short g_WoutB[(size_t)G * 1024 * JTILE + 4096]; // bf16 [tile][k][112] (+prefetch pad)
__device__ __align__(16) float g_WoutV[(size_t)16416 * 1024];                     // fp32 [v][k]
__device__ __align__(16) float g_Wl[(size_t)128 * 1024 * 64 + 512];               // [tile][k][wx32|wh32] (+pad)
__device__ __align__(16) float g_WpT[H * H];                                      // [j][k]
__device__ float g_h[B * H];
__device__ float g_c[B * H];
__device__ float g_h2[2][B * H];
__device__ float g_c2[2][B * H];
__device__ float g_qkb[H * B];     // q in [j][b]
__device__ float g_qbj[B * H];     // q in [b][j]
__device__ int   g_lastbuf[2][B];
__device__ int   g_advbuf[2][B];
__device__ unsigned long long g_afin[B];
__device__ unsigned g_leaf[8];
__device__ unsigned g_root;
__device__ unsigned g_gen;

// ---------------- helpers ----------------
__device__ __forceinline__ unsigned long long ffma2(unsigned long long a,
                                                    unsigned long long b,
                                                    unsigned long long c) {
    unsigned long long d;
    asm("fma.rn.f32x2 %0, %1, %2, %3;" : "=l"(d) : "l"(a), "l"(b), "l"(c));
    return d;
}
__device__ __forceinline__ unsigned long long dup2(float w) {
    unsigned long long r;
    unsigned u = __float_as_uint(w);
    asm("mov.b64 %0, {%1, %1};" : "=l"(r) : "r"(u));
    return r;
}
__device__ __forceinline__ unsigned long long dup2lo(unsigned a) {
    unsigned f = a << 16; unsigned long long r;
    asm("mov.b64 %0, {%1, %1};" : "=l"(r) : "r"(f));
    return r;
}
__device__ __forceinline__ unsigned long long dup2hi(unsigned a) {
    unsigned f = a & 0xFFFF0000u; unsigned long long r;
    asm("mov.b64 %0, {%1, %1};" : "=l"(r) : "r"(f));
    return r;
}
__device__ __forceinline__ unsigned long long pack_key(float f, int v) {
    unsigned u = __float_as_uint(f);
    u = (u & 0x80000000u) ? ~u : (u | 0x80000000u);
    return ((unsigned long long)u << 32) | (unsigned)(BLANK - v);
}
__device__ __forceinline__ float sigm(float x) { return 1.0f / (1.0f + expf(-x)); }

__device__ __forceinline__ void grid_sync(int bid) {
    __syncthreads();
    if (threadIdx.x == 0) {
        __threadfence();
        unsigned gen = *(volatile unsigned*)&g_gen;
        int leaf = bid & 7;
        unsigned cnt = (leaf < 4) ? 19u : 18u;
        unsigned t = atomicAdd(&g_leaf[leaf], 1u);
        if ((t % cnt) == cnt - 1u) {
            unsigned rt = atomicAdd(&g_root, 1u);
            if ((rt & 7u) == 7u) {
                __threadfence();
                atomicExch(&g_gen, gen + 1u);
            }
        }
        while (*(volatile unsigned*)&g_gen == gen) {}
        __threadfence();
    }
    __syncthreads();
}

// ---------------- setup kernels ----------------
__global__ void k_setup1(const float* __restrict__ enc, const float* __restrict__ W_pred) {
    __shared__ float tile[32][33];
    int bidx = blockIdx.x;
    int tx = threadIdx.x, ty = threadIdx.y;   // 32 x 8
    if (bidx < 1792) {
        int b = bidx & 7, kb = ((bidx >> 3) & 31) * 32, tb = (bidx >> 8) * 32;
#pragma unroll
        for (int i = 0; i < 4; i++) {
            int k = kb + ty + i * 8, t = tb + tx;
            tile[ty + i * 8][tx] = (t < T) ? enc[(size_t)b * H * T + (size_t)k * T + t] : 0.0f;
        }
        __syncthreads();
#pragma unroll
        for (int i = 0; i < 4; i++) {
            int t = tb + ty + i * 8, k = kb + tx;
            if (t < T) g_encT[((size_t)t * B + b) * H + k] = tile[tx][ty + i * 8];
        }
        if (bidx == 0) {
            int tid = ty * 32 + tx;
            for (int i = tid; i < B * H; i += 256) { g_h[i] = 0.0f; g_c[i] = 0.0f; }
            if (tid < B) g_afin[tid] = 0ull;
        }
    } else {
        int j = bidx - 1792;
        int kb = (j & 31) * 32, jb = (j >> 5) * 32;
#pragma unroll
        for (int i = 0; i < 4; i++)
            tile[ty + i * 8][tx] = W_pred[(size_t)(kb + ty + i * 8) * H + jb + tx];
        __syncthreads();
#pragma unroll
        for (int i = 0; i < 4; i++)
            g_WpT[(size_t)(jb + ty + i * 8) * H + kb + tx] = tile[tx][ty + i * 8];
    }
}

__global__ void k_setup2(const float* __restrict__ W_out, const float* __restrict__ Wx,
                         const float* __restrict__ Wh) {
    __shared__ float tile[32][33];
    int bid = blockIdx.x;
    int tid = threadIdx.x;   // 256
    if (bid < G * 1024) {
        int tileI = bid >> 10, k = bid & 1023;
        if (tid < JTILE) {
            int v = tileI * JTILE + tid;
            float val = (v < NV) ? W_out[(size_t)k * NV + v] : 0.0f;
            g_WoutB[((size_t)tileI * 1024 + k) * JTILE + tid] =
                __bfloat16_as_ushort(__float2bfloat16(val));
        }
    } else if (bid < G * 1024 + 128 * 1024) {
        int j = bid - G * 1024;
        int tileI = j >> 10, k = j & 1023;
        if (tid < 64) {
            float val;
            if (tid < 32) val = Wx[(size_t)k * 4096 + (tid >> 3) * 1024 + tileI * 8 + (tid & 7)];
            else { int l2 = tid - 32; val = Wh[(size_t)k * 4096 + (l2 >> 3) * 1024 + tileI * 8 + (l2 & 7)]; }
            g_Wl[((size_t)tileI * 1024 + k) * 64 + tid] = val;
        }
    } else {
        int j = bid - (G * 1024 + 128 * 1024);
        int tile_k = j / 513, tile_v = j - tile_k * 513;
        int kb = tile_k * 32, vb = tile_v * 32;
        int tx = tid & 31, ty = tid >> 5;   // 32 x 8
#pragma unroll
        for (int i = 0; i < 4; i++) {
            int k = kb + ty + i * 8, v = vb + tx;
            tile[ty + i * 8][tx] = (v < NV) ? W_out[(size_t)k * NV + v] : 0.0f;
        }
        __syncthreads();
#pragma unroll
        for (int i = 0; i < 4; i++) {
            int v = vb + ty + i * 8, k = kb + tx;
            g_WoutV[(size_t)v * 1024 + k] = tile[tx][ty + i * 8];
        }
    }
}

__global__ void k_egemm(const float* __restrict__ W_enc, const float* __restrict__ b_joint) {
    __shared__ float xs[B * H];
    int t = blockIdx.y;
    int j = blockIdx.x * 256 + threadIdx.x;
    for (int idx = threadIdx.x; idx < B * H; idx += 256)
        xs[idx] = g_encT[(size_t)t * B * H + idx];
    __syncthreads();
    float acc[B];
#pragma unroll
    for (int b = 0; b < B; b++) acc[b] = 0.0f;
    for (int k = 0; k < H; k += 4) {
        float w0 = __ldg(&W_enc[(size_t)(k + 0) * H + j]);
        float w1 = __ldg(&W_enc[(size_t)(k + 1) * H + j]);
        float w2 = __ldg(&W_enc[(size_t)(k + 2) * H + j]);
        float w3 = __ldg(&W_enc[(size_t)(k + 3) * H + j]);
#pragma unroll
        for (int b = 0; b < B; b++) {
            float4 q4 = *(const float4*)&xs[b * H + k];
            acc[b] = fmaf(q4.x, w0, acc[b]);
            acc[b] = fmaf(q4.y, w1, acc[b]);
            acc[b] = fmaf(q4.z, w2, acc[b]);
            acc[b] = fmaf(q4.w, w3, acc[b]);
        }
    }
    float bj = __ldg(&b_joint[j]);
#pragma unroll
    for (int b = 0; b < B; b++)
        g_E[((size_t)t * B + b) * H + j] = acc[b] + bj;
}

// ---------------- persistent decode kernel ----------------
// smem floats:
//  A [0,8192): xs (LSTM) / h2 stage (pred) / qs (joint)
//  B [8192,16384): hs (LSTM) / prsh (pred)
//  C [16384,32768): redu
//  D [32768,33024): zs (LSTM)
//  E [33024,33920): logf (joint)  [33920,33984): spart
#define SMEM_FLOATS 33984

__global__ void __launch_bounds__(NTHR, 1)
k_decode(const float* __restrict__ emb, const float* __restrict__ bias,
         const float* __restrict__ b_out,
         const int* __restrict__ lens, float* __restrict__ out) {
    extern __shared__ float sm[];
    __shared__ int s_adv[8];
    __shared__ int s_last[8];
    __shared__ float s_gmax[8];
    __shared__ int s_ncand;
    __shared__ int s_cand[896];
    int tid = threadIdx.x, bid = blockIdx.x;

    for (int s = 0; s < NSTEP; s++) {
        int p = s & 1;
        int is_start = (s == 0);

        // ---- decisions for step s-1 (g_afin is exact fp32 argmax) ----
        if (tid < 8) {
            int b = tid, advance = 0, lastv = BLANK;
            if (s > 0) {
                int d = s - 1, dp = d & 1;
                unsigned long long key = g_afin[b];
                int sym = BLANK - (int)(unsigned)(key & 0xffffffffu);
                int t = d >> 2, u = d & 3;
                int active = (u == 0) ? (t < lens[b]) : g_advbuf[dp ^ 1][b];
                advance = (active && sym != BLANK) ? 1 : 0;
                int prev_last = (d == 0) ? BLANK : g_lastbuf[dp ^ 1][b];
                lastv = advance ? sym : prev_last;
                g_advbuf[dp][b] = advance;
                g_lastbuf[dp][b] = lastv;
                if (bid == 0)
                    out[(size_t)b * NSTEP + t * MAXSYM + u] = (float)(active ? sym : BLANK);
            }
            s_adv[tid] = advance;
            s_last[tid] = lastv;
        }
        __syncthreads();

        // ---- LSTM (blocks 0..127, 8 hidden cols each) ----
        if (bid < 128) {
            const float* h2prev = g_h2[p ^ 1];
            float* xs = sm;
            float* hs = sm + 8192;
#pragma unroll
            for (int bb = 0; bb < 8; bb++) {
                int adv = s_adv[bb];
                const float* hsrc = adv ? (h2prev + bb * H) : (g_h + bb * H);
                const float* xsrc = emb + (size_t)s_last[bb] * H;
                int k = tid;
                float hv = 0.0f, xv = 0.0f;
                if (!is_start) { hv = hsrc[k]; xv = __ldg(&xsrc[k]); }
                hs[k * 8 + bb] = hv;
                xs[k * 8 + bb] = xv;
            }
            __syncthreads();
            if (tid < 64) {   // commit h
                int idx = bid * 64 + tid;
                int b = idx >> 10, k = idx & 1023;
                g_h[idx] = hs[k * 8 + b];
            }

            {
                int kp = tid >> 5;        // 32 k-chunks of 32
                int jg = tid & 31;        // gate-col pair (jg<16 wx, >=16 wh)
                const float2* wp2 = (const float2*)(g_Wl + ((size_t)bid * 1024) * 64) + jg;
                const unsigned long long* xh =
                    (jg < 16) ? (const unsigned long long*)xs : (const unsigned long long*)hs;
                unsigned long long acc[2][4];
#pragma unroll
                for (int c = 0; c < 2; c++)
#pragma unroll
                    for (int bp = 0; bp < 4; bp++) acc[c][bp] = 0ull;
                int k0 = kp * 32;
                float2 buf[4];   // depth-4 prefetch ring
#pragma unroll
                for (int i = 0; i < 4; i++) buf[i] = wp2[(size_t)(k0 + i) * 32];
#pragma unroll
                for (int kk = 0; kk < 32; kk += 4) {
#pragma unroll
                    for (int i = 0; i < 4; i++) {
                        float2 w = buf[i];
                        buf[i] = wp2[(size_t)(k0 + kk + 4 + i) * 32];
                        int k = k0 + kk + i;
                        unsigned long long w0 = dup2(w.x), w1 = dup2(w.y);
#pragma unroll
                        for (int bp = 0; bp < 4; bp++) {
                            unsigned long long xp = xh[k * 4 + bp];
                            acc[0][bp] = ffma2(xp, w0, acc[0][bp]);
                            acc[1][bp] = ffma2(xp, w1, acc[1][bp]);
                        }
                    }
                }
                unsigned long long* redu = (unsigned long long*)(sm + 16384);
#pragma unroll
                for (int c = 0; c < 2; c++)
#pragma unroll
                    for (int bp = 0; bp < 4; bp++)
                        redu[(c * 4 + bp) * NTHR + tid] = acc[c][bp];
            }
            __syncthreads();
            if (tid < 256) {   // 32 gate-cols x 8 b
                int gc = tid >> 3, b = tid & 7;
                int jgx = gc >> 1, cc = gc & 1;
                int bp = b >> 1, half = b & 1;
                const float* redf = sm + 16384;
                float z = 0.0f;
#pragma unroll 8
                for (int kp = 0; kp < 32; kp++) {
                    z += redf[((cc * 4 + bp) * NTHR + kp * 32 + jgx) * 2 + half];
                    z += redf[((cc * 4 + bp) * NTHR + kp * 32 + 16 + jgx) * 2 + half];
                }
                int gate = gc >> 3, ch = gc & 7;
                z += __ldg(&bias[gate * 1024 + bid * 8 + ch]);
                float* zs = sm + 32768;
                zs[gc * 8 + b] = z;
            }
            __syncthreads();
            if (tid < 64) {
                int b = tid & 7, ch = tid >> 3;
                int jh = bid * 8 + ch;
                const float* zs = sm + 32768;
                float zi = zs[(0 * 8 + ch) * 8 + b];
                float zf = zs[(1 * 8 + ch) * 8 + b];
                float zg = zs[(2 * 8 + ch) * 8 + b];
                float zo = zs[(3 * 8 + ch) * 8 + b];
                float c_eff = 0.0f;
                if (!is_start) c_eff = s_adv[b] ? g_c2[p ^ 1][b * H + jh] : g_c[b * H + jh];
                g_c[b * H + jh] = c_eff;
                float cn = sigm(zf) * c_eff + sigm(zi) * tanhf(zg);
                float hn = sigm(zo) * tanhf(cn);
                g_c2[p][b * H + jh] = cn;
                g_h2[p][b * H + jh] = hn;
            }
        }
        grid_sync(bid);

        // ---- pred (blocks 0..127, 8 j each); block 128 resets g_afin ----
        if (bid < 128) {
            const float* h2c = g_h2[p];
#pragma unroll
            for (int bb = 0; bb < 8; bb++) {
                int k = tid;
                sm[k * 8 + bb] = h2c[bb * H + k];
            }
            __syncthreads();
            int w = tid >> 5, lane = tid & 31;
            int jloc = w & 7, q4 = w >> 3;       // 8 j x 4 k-quarters
            int j = bid * 8 + jloc;
            const float4* wp = (const float4*)(g_WpT + (size_t)j * H + q4 * 256);
            const unsigned long long* hu = (const unsigned long long*)sm;
            // hoist both loads (MLP=2 up front)
            float4 wA = wp[lane];
            float4 wB = wp[32 + lane];
            unsigned long long acc[4];
#pragma unroll
            for (int bp = 0; bp < 4; bp++) acc[bp] = 0ull;
#pragma unroll
            for (int cIt = 0; cIt < 2; cIt++) {
                int k = q4 * 256 + cIt * 128 + lane * 4;
                float4 w4 = (cIt == 0) ? wA : wB;
                unsigned long long w0 = dup2(w4.x), w1 = dup2(w4.y);
                unsigned long long w2 = dup2(w4.z), w3 = dup2(w4.w);
#pragma unroll
                for (int bp = 0; bp < 4; bp++) {
                    acc[bp] = ffma2(hu[(k + 0) * 4 + bp], w0, acc[bp]);
                    acc[bp] = ffma2(hu[(k + 1) * 4 + bp], w1, acc[bp]);
                    acc[bp] = ffma2(hu[(k + 2) * 4 + bp], w2, acc[bp]);
                    acc[bp] = ffma2(hu[(k + 3) * 4 + bp], w3, acc[bp]);
                }
            }
            float a[8];
#pragma unroll
            for (int bp = 0; bp < 4; bp++) {
                unsigned lo, hi;
                asm("mov.b64 {%0, %1}, %2;" : "=r"(lo), "=r"(hi) : "l"(acc[bp]));
                a[bp * 2] = __uint_as_float(lo);
                a[bp * 2 + 1] = __uint_as_float(hi);
            }
#pragma unroll
            for (int off = 16; off > 0; off >>= 1)
#pragma unroll
                for (int b = 0; b < 8; b++)
                    a[b] += __shfl_down_sync(0xffffffffu, a[b], off);
            float* prsh = sm + 8192;
            if (lane == 0) {
#pragma unroll
                for (int b = 0; b < 8; b++)
                    prsh[q4 * 64 + jloc * 8 + b] = a[b];
            }
            __syncthreads();
            if (tid < 64) {
                int jl = tid >> 3, b = tid & 7;
                int jj = bid * 8 + jl;
                int t = s >> 2;
                float v = prsh[jl * 8 + b] + prsh[64 + jl * 8 + b]
                        + prsh[128 + jl * 8 + b] + prsh[192 + jl * 8 + b]
                        + g_E[((size_t)t * B + b) * H + jj];
                float qv = tanhf(v);
                g_qkb[jj * 8 + b] = qv;
                g_qbj[b * 1024 + jj] = qv;
            }
        } else if (bid == 128) {
            if (tid < 8) g_afin[tid] = 0ull;
        }
        grid_sync(bid);

        // ---- joint: bf16 logits + block-local fp32 re-check -> exact g_afin ----
        {
            float* qs = sm;
            for (int i = tid; i < H * B; i += NTHR) qs[i] = g_qkb[i];
            __syncthreads();
            const unsigned long long* qu = (const unsigned long long*)qs;
            int kc = tid >> 6;        // 16 k-chunks of 64
            int vg = tid & 63;        // <56 active: cols vg*2, vg*2+1
            unsigned long long acc[2][4];
#pragma unroll
            for (int c = 0; c < 2; c++)
#pragma unroll
                for (int bp = 0; bp < 4; bp++) acc[c][bp] = 0ull;
            if (vg < 56) {
                const unsigned short* wt = g_WoutB + ((size_t)bid * 1024) * JTILE + vg * 2;
                int k0 = kc * 64;
                unsigned buf[8];   // depth-8 prefetch ring
#pragma unroll
                for (int i = 0; i < 8; i++)
                    buf[i] = *(const unsigned*)&wt[(size_t)(k0 + i) * JTILE];
#pragma unroll
                for (int kk = 0; kk < 64; kk += 8) {
#pragma unroll
                    for (int i = 0; i < 8; i++) {
                        unsigned wv = buf[i];
                        buf[i] = *(const unsigned*)&wt[(size_t)(k0 + kk + 8 + i) * JTILE];
                        int k = k0 + kk + i;
                        unsigned long long w0 = dup2lo(wv), w1 = dup2hi(wv);
#pragma unroll
                        for (int bp = 0; bp < 4; bp++) {
                            unsigned long long qp = qu[k * 4 + bp];
                            acc[0][bp] = ffma2(qp, w0, acc[0][bp]);
                            acc[1][bp] = ffma2(qp, w1, acc[1][bp]);
                        }
                    }
                }
            }
            unsigned long long* redu = (unsigned long long*)(sm + 16384);
            const float* redf = sm + 16384;
#pragma unroll
            for (int c = 0; c < 2; c++)
#pragma unroll
                for (int bp = 0; bp < 4; bp++)
                    redu[(c * 4 + bp) * NTHR + tid] = acc[c][bp];
            __syncthreads();
            float* logf = sm + 33024;
            for (int o = tid; o < JTILE * 8; o += NTHR) {
                int b = o / JTILE, col = o - b * JTILE;
                int vg2 = col >> 1, cc = col & 1, bp = b >> 1, half = b & 1;
                float sv = 0.0f;
#pragma unroll
                for (int kc2 = 0; kc2 < 16; kc2++)
                    sv += redf[((cc * 4 + bp) * NTHR + kc2 * 64 + vg2) * 2 + half];
                int v = bid * JTILE + col;
                logf[o] = (v < NV) ? sv + __ldg(&b_out[v]) : -1e30f;
            }
            __syncthreads();
            // block-local max per b
            float* spart = sm + 33920;
            if (tid < 64) {
                int b = tid >> 3, part = tid & 7;
                float m = -1e30f;
#pragma unroll
                for (int cc = 0; cc < 14; cc++)
                    m = fmaxf(m, logf[b * JTILE + part * 14 + cc]);
                spart[tid] = m;
            }
            __syncthreads();
            if (tid < 8) {
                float m = -1e30f;
#pragma unroll
                for (int pp = 0; pp < 8; pp++) m = fmaxf(m, spart[tid * 8 + pp]);
                s_gmax[tid] = m;
            }
            if (tid == 0) s_ncand = 0;
            __syncthreads();
            // candidate scan (superset of global-max candidates) + exact fp32 dots
            for (int o = tid; o < JTILE * 8; o += NTHR) {
                int b = o / JTILE;
                if (logf[o] >= s_gmax[b] - DELTA) {
                    int i = atomicAdd(&s_ncand, 1);
                    s_cand[i] = (b << 16) | (bid * JTILE + (o - b * JTILE));
                }
            }
            __syncthreads();
            int nc = s_ncand;
            int w2 = tid >> 5, ln = tid & 31;
            for (int ci = w2; ci < nc; ci += 32) {
                int pk = s_cand[ci];
                int b = pk >> 16, v = pk & 0xffff;
                if (v < NV) {
                    const float* wv = g_WoutV + (size_t)v * 1024;
                    const float* qv = g_qbj + b * 1024;
                    float part = 0.0f;
#pragma unroll 8
                    for (int kk = ln; kk < 1024; kk += 32)
                        part = fmaf(wv[kk], qv[kk], part);
#pragma unroll
                    for (int off = 16; off > 0; off >>= 1)
                        part += __shfl_down_sync(0xffffffffu, part, off);
                    if (ln == 0)
                        atomicMax(&g_afin[b], pack_key(part + __ldg(&b_out[v]), v));
                }
            }
        }
        grid_sync(bid);
    }

    // ---- epilogue: final decision + h,c output ----
    {
        int d = NSTEP - 1, dp = d & 1;
        if (tid < 8) {
            int b = tid;
            unsigned long long key = g_afin[b];
            int sym = BLANK - (int)(unsigned)(key & 0xffffffffu);
            int t = d >> 2, u = d & 3;
            int active = (u == 0) ? (t < lens[b]) : g_advbuf[dp ^ 1][b];
            int advance = (active && sym != BLANK) ? 1 : 0;
            if (bid == 0)
                out[(size_t)b * NSTEP + t * MAXSYM + u] = (float)(active ? sym : BLANK);
            s_adv[tid] = advance;
        }
        __syncthreads();
        for (int i = bid * NTHR + tid; i < B * H; i += G * NTHR) {
            int b = i >> 10;
            float hf = s_adv[b] ? g_h2[dp][i] : g_h[i];
            float cf = s_adv[b] ? g_c2[dp][i] : g_c[i];
            out[B * NSTEP + i] = hf;
            out[B * NSTEP + B * H + i] = cf;
        }
    }
}

extern "C" void kernel_launch(void* const* d_in, const int* in_sizes, int n_in,
                              void* d_out, int out_size) {
    (void)in_sizes; (void)n_in; (void)out_size;
    const float* enc     = (const float*)d_in[0];
    const int*   lens    = (const int*)d_in[1];
    const float* emb     = (const float*)d_in[2];
    const float* Wx      = (const float*)d_in[3];
    const float* Wh      = (const float*)d_in[4];
    const float* bias    = (const float*)d_in[5];
    const float* W_enc   = (const float*)d_in[6];
    const float* W_pred  = (const float*)d_in[7];
    const float* b_joint = (const float*)d_in[8];
    const float* W_out   = (const float*)d_in[9];
    const float* b_out   = (const float*)d_in[10];
    float* out = (float*)d_out;

    static int configured = 0;
    if (!configured) {
        cudaFuncSetAttribute(k_decode, cudaFuncAttributeMaxDynamicSharedMemorySize,
                             SMEM_FLOATS * 4);
        configured = 1;
    }

    k_setup1<<<2816, dim3(32, 8)>>>(enc, W_pred);
    k_setup2<<<G * 1024 + 128 * 1024 + 513 * 32, 256>>>(W_out, Wx, Wh);
    k_egemm<<<dim3(4, T), 256>>>(W_enc, b_joint);
    k_decode<<<G, NTHR, SMEM_FLOATS * 4>>>(emb, bias, b_out, lens, out);
}

// round 10
// speedup vs baseline: 1.4304x; 1.1021x over previous
#include <cuda_runtime.h>
#include <cuda_bf16.h>
#include <math.h>

// RNN-T greedy decode, persistent kernel, 1024 thr/block.
// LSTM/pred fp32; joint via bf16 mma.sync (HMMA) + in-phase exact fp32 re-check.
#define B 8
#define T 200
#define H 1024
#define NV 16385
#define BLANK 16384
#define MAXSYM 4
#define NSTEP (T * MAXSYM) // 800
#define G 148
#define NTHR 1024
#define JTILE 112          // vocab cols per block (148*112 = 16576 >= NV)
#define DELTA 0.0625f

// ---------------- device scratch ----------------
__device__ __align__(16) float g_encT[T * B * H];
__device__ __align__(16) float g_E[T * B * H];
// mma-packed W_out: per (tile, kt16): 14 coltiles x 32 u64; u64 = (b0,b1) frags
__device__ __align__(16) unsigned g_WoutM[(size_t)G * 64 * 896 + 8192];
__device__ __align__(16) float g_WoutV[(size_t)16416 * 1024];          // fp32 [v][k] re-check
__device__ __align__(16) float g_Wl[(size_t)128 * 1024 * 64 + 512];    // [tile][k][wx32|wh32]
__device__ __align__(16) float g_WpT[H * H];                            // [j][k]
__device__ float g_h[B * H];
__device__ float g_c[B * H];
__device__ float g_h2[2][B * H];
__device__ float g_c2[2][B * H];
__device__ unsigned g_qmma[4096];  // q bf16x2: [kp(512)][b(8)]
__device__ float g_qbj[B * H];     // q fp32 [b][j] (re-check)
__device__ int   g_lastbuf[2][B];
__device__ int   g_advbuf[2][B];
__device__ unsigned long long g_afin[B];
__device__ unsigned g_leaf[8];
__device__ unsigned g_root;
__device__ unsigned g_gen;

// ---------------- helpers ----------------
__device__ __forceinline__ unsigned long long ffma2(unsigned long long a,
                                                    unsigned long long b,
                                                    unsigned long long c) {
    unsigned long long d;
    asm("fma.rn.f32x2 %0, %1, %2, %3;" : "=l"(d) : "l"(a), "l"(b), "l"(c));
    return d;
}
__device__ __forceinline__ unsigned long long dup2(float w) {
    unsigned long long r;
    unsigned u = __float_as_uint(w);
    asm("mov.b64 %0, {%1, %1};" : "=l"(r) : "r"(u));
    return r;
}
__device__ __forceinline__ unsigned long long pack_key(float f, int v) {
    unsigned u = __float_as_uint(f);
    u = (u & 0x80000000u) ? ~u : (u | 0x80000000u);
    return ((unsigned long long)u << 32) | (unsigned)(BLANK - v);
}
__device__ __forceinline__ float sigm(float x) { return 1.0f / (1.0f + expf(-x)); }

__device__ __forceinline__ void grid_sync(int bid) {
    __syncthreads();
    if (threadIdx.x == 0) {
        __threadfence();
        unsigned gen = *(volatile unsigned*)&g_gen;
        int leaf = bid & 7;
        unsigned cnt = (leaf < 4) ? 19u : 18u;
        unsigned t = atomicAdd(&g_leaf[leaf], 1u);
        if ((t % cnt) == cnt - 1u) {
            unsigned rt = atomicAdd(&g_root, 1u);
            if ((rt & 7u) == 7u) {
                __threadfence();
                atomicExch(&g_gen, gen + 1u);
            }
        }
        while (*(volatile unsigned*)&g_gen == gen) {}
        __threadfence();
    }
    __syncthreads();
}

// ---------------- setup kernels ----------------
__global__ void k_setup1(const float* __restrict__ enc, const float* __restrict__ W_pred) {
    __shared__ float tile[32][33];
    int bidx = blockIdx.x;
    int tx = threadIdx.x, ty = threadIdx.y;   // 32 x 8
    if (bidx < 1792) {
        int b = bidx & 7, kb = ((bidx >> 3) & 31) * 32, tb = (bidx >> 8) * 32;
#pragma unroll
        for (int i = 0; i < 4; i++) {
            int k = kb + ty + i * 8, t = tb + tx;
            tile[ty + i * 8][tx] = (t < T) ? enc[(size_t)b * H * T + (size_t)k * T + t] : 0.0f;
        }
        __syncthreads();
#pragma unroll
        for (int i = 0; i < 4; i++) {
            int t = tb + ty + i * 8, k = kb + tx;
            if (t < T) g_encT[((size_t)t * B + b) * H + k] = tile[tx][ty + i * 8];
        }
        if (bidx == 0) {
            int tid = ty * 32 + tx;
            for (int i = tid; i < B * H; i += 256) { g_h[i] = 0.0f; g_c[i] = 0.0f; }
            if (tid < B) g_afin[tid] = 0ull;
        }
    } else {
        int j = bidx - 1792;
        int kb = (j & 31) * 32, jb = (j >> 5) * 32;
#pragma unroll
        for (int i = 0; i < 4; i++)
            tile[ty + i * 8][tx] = W_pred[(size_t)(kb + ty + i * 8) * H + jb + tx];
        __syncthreads();
#pragma unroll
        for (int i = 0; i < 4; i++)
            g_WpT[(size_t)(jb + ty + i * 8) * H + kb + tx] = tile[tx][ty + i * 8];
    }
}

// segments: [0,9472) mma W_out pack ; [9472, +131072) Wl ; rest: W_out -> [v][k]
__global__ void k_setup2(const float* __restrict__ W_out, const float* __restrict__ Wx,
                         const float* __restrict__ Wh) {
    __shared__ float tile[32][33];
    int bid = blockIdx.x;
    int tid = threadIdx.x;   // 448
    if (bid < G * 64) {
        int tileI = bid >> 6, kt = bid & 63;
        if (tid < 448) {
            int ct = tid >> 5, r = tid & 31;
            int cloc = r >> 2, pq = r & 3;
            int v = tileI * JTILE + ct * 8 + cloc;
            int k0 = kt * 16 + 2 * pq;
            unsigned e[4];
#pragma unroll
            for (int i = 0; i < 4; i++) {
                int kk = (i < 2) ? (k0 + i) : (k0 + 6 + i);   // k0, k0+1, k0+8, k0+9
                float f = (v < NV) ? W_out[(size_t)kk * NV + v] : 0.0f;
                e[i] = (unsigned)__bfloat16_as_ushort(__float2bfloat16(f));
            }
            size_t idx64 = (size_t)bid * 448 + ct * 32 + r;
            g_WoutM[idx64 * 2 + 0] = (e[1] << 16) | e[0];
            g_WoutM[idx64 * 2 + 1] = (e[3] << 16) | e[2];
        }
    } else if (bid < G * 64 + 128 * 1024) {
        int j = bid - G * 64;
        int tileI = j >> 10, k = j & 1023;
        if (tid < 64) {
            float val;
            if (tid < 32) val = Wx[(size_t)k * 4096 + (tid >> 3) * 1024 + tileI * 8 + (tid & 7)];
            else { int l2 = tid - 32; val = Wh[(size_t)k * 4096 + (l2 >> 3) * 1024 + tileI * 8 + (l2 & 7)]; }
            g_Wl[((size_t)tileI * 1024 + k) * 64 + tid] = val;
        }
    } else if (tid < 256) {
        int j = bid - (G * 64 + 128 * 1024);
        int tile_k = j / 513, tile_v = j - tile_k * 513;
        int kb = tile_k * 32, vb = tile_v * 32;
        int tx = tid & 31, ty = tid >> 5;   // 32 x 8
#pragma unroll
        for (int i = 0; i < 4; i++) {
            int k = kb + ty + i * 8, v = vb + tx;
            tile[ty + i * 8][tx] = (v < NV) ? W_out[(size_t)k * NV + v] : 0.0f;
        }
        __syncthreads();
#pragma unroll
        for (int i = 0; i < 4; i++) {
            int v = vb + ty + i * 8, k = kb + tx;
            g_WoutV[(size_t)v * 1024 + k] = tile[tx][ty + i * 8];
        }
    }
}

__global__ void k_egemm(const float* __restrict__ W_enc, const float* __restrict__ b_joint) {
    __shared__ float xs[B * H];
    int t = blockIdx.y;
    int j = blockIdx.x * 256 + threadIdx.x;
    for (int idx = threadIdx.x; idx < B * H; idx += 256)
        xs[idx] = g_encT[(size_t)t * B * H + idx];
    __syncthreads();
    float acc[B];
#pragma unroll
    for (int b = 0; b < B; b++) acc[b] = 0.0f;
    for (int k = 0; k < H; k += 4) {
        float w0 = __ldg(&W_enc[(size_t)(k + 0) * H + j]);
        float w1 = __ldg(&W_enc[(size_t)(k + 1) * H + j]);
        float w2 = __ldg(&W_enc[(size_t)(k + 2) * H + j]);
        float w3 = __ldg(&W_enc[(size_t)(k + 3) * H + j]);
#pragma unroll
        for (int b = 0; b < B; b++) {
            float4 q4 = *(const float4*)&xs[b * H + k];
            acc[b] = fmaf(q4.x, w0, acc[b]);
            acc[b] = fmaf(q4.y, w1, acc[b]);
            acc[b] = fmaf(q4.z, w2, acc[b]);
            acc[b] = fmaf(q4.w, w3, acc[b]);
        }
    }
    float bj = __ldg(&b_joint[j]);
#pragma unroll
    for (int b = 0; b < B; b++)
        g_E[((size_t)t * B + b) * H + j] = acc[b] + bj;
}

// ---------------- persistent decode kernel ----------------
// smem floats:
//  LSTM : xs[0,8192) hs[8192,16384) redu[16384,32768) zs[32768,33024)
//  pred : h2kb[0,8192) prsh @8192
//  joint: qsm u32 [0,4096) ; ppart [16384,18176) ; logf [33024,33920) ; spart [33920,33984)
#define SMEM_FLOATS 33984

__global__ void __launch_bounds__(NTHR, 1)
k_decode(const float* __restrict__ emb, const float* __restrict__ bias,
         const float* __restrict__ b_out,
         const int* __restrict__ lens, float* __restrict__ out) {
    extern __shared__ float sm[];
    __shared__ int s_adv[8];
    __shared__ int s_last[8];
    __shared__ float s_gmax[8];
    __shared__ int s_ncand;
    __shared__ int s_cand[896];
    int tid = threadIdx.x, bid = blockIdx.x;

    for (int s = 0; s < NSTEP; s++) {
        int p = s & 1;
        int is_start = (s == 0);

        // ---- decisions for step s-1 (g_afin is exact fp32 argmax) ----
        if (tid < 8) {
            int b = tid, advance = 0, lastv = BLANK;
            if (s > 0) {
                int d = s - 1, dp = d & 1;
                unsigned long long key = g_afin[b];
                int sym = BLANK - (int)(unsigned)(key & 0xffffffffu);
                int t = d >> 2, u = d & 3;
                int active = (u == 0) ? (t < lens[b]) : g_advbuf[dp ^ 1][b];
                advance = (active && sym != BLANK) ? 1 : 0;
                int prev_last = (d == 0) ? BLANK : g_lastbuf[dp ^ 1][b];
                lastv = advance ? sym : prev_last;
                g_advbuf[dp][b] = advance;
                g_lastbuf[dp][b] = lastv;
                if (bid == 0)
                    out[(size_t)b * NSTEP + t * MAXSYM + u] = (float)(active ? sym : BLANK);
            }
            s_adv[tid] = advance;
            s_last[tid] = lastv;
        }
        __syncthreads();

        // ---- LSTM (blocks 0..127) ----
        if (bid < 128) {
            const float* h2prev = g_h2[p ^ 1];
            float* xs = sm;
            float* hs = sm + 8192;
#pragma unroll
            for (int bb = 0; bb < 8; bb++) {
                int adv = s_adv[bb];
                const float* hsrc = adv ? (h2prev + bb * H) : (g_h + bb * H);
                const float* xsrc = emb + (size_t)s_last[bb] * H;
                int k = tid;
                float hv = 0.0f, xv = 0.0f;
                if (!is_start) { hv = hsrc[k]; xv = __ldg(&xsrc[k]); }
                hs[k * 8 + bb] = hv;
                xs[k * 8 + bb] = xv;
            }
            __syncthreads();
            if (tid < 64) {   // commit h
                int idx = bid * 64 + tid;
                int b = idx >> 10, k = idx & 1023;
                g_h[idx] = hs[k * 8 + b];
            }

            {
                int kp = tid >> 5;        // 32 k-chunks of 32
                int jg = tid & 31;        // gate-col pair (jg<16 wx, >=16 wh)
                const float2* wp2 = (const float2*)(g_Wl + ((size_t)bid * 1024) * 64) + jg;
                const unsigned long long* xh =
                    (jg < 16) ? (const unsigned long long*)xs : (const unsigned long long*)hs;
                unsigned long long acc[2][4];
#pragma unroll
                for (int c = 0; c < 2; c++)
#pragma unroll
                    for (int bp = 0; bp < 4; bp++) acc[c][bp] = 0ull;
                int k0 = kp * 32;
                float2 buf[4];
#pragma unroll
                for (int i = 0; i < 4; i++) buf[i] = wp2[(size_t)(k0 + i) * 32];
#pragma unroll
                for (int kk = 0; kk < 32; kk += 4) {
#pragma unroll
                    for (int i = 0; i < 4; i++) {
                        float2 w = buf[i];
                        buf[i] = wp2[(size_t)(k0 + kk + 4 + i) * 32];
                        int k = k0 + kk + i;
                        unsigned long long w0 = dup2(w.x), w1 = dup2(w.y);
#pragma unroll
                        for (int bp = 0; bp < 4; bp++) {
                            unsigned long long xp = xh[k * 4 + bp];
                            acc[0][bp] = ffma2(xp, w0, acc[0][bp]);
                            acc[1][bp] = ffma2(xp, w1, acc[1][bp]);
                        }
                    }
                }
                unsigned long long* redu = (unsigned long long*)(sm + 16384);
#pragma unroll
                for (int c = 0; c < 2; c++)
#pragma unroll
                    for (int bp = 0; bp < 4; bp++)
                        redu[(c * 4 + bp) * NTHR + tid] = acc[c][bp];
            }
            __syncthreads();
            if (tid < 256) {
                int gc = tid >> 3, b = tid & 7;
                int jgx = gc >> 1, cc = gc & 1;
                int bp = b >> 1, half = b & 1;
                const float* redf = sm + 16384;
                float z = 0.0f;
#pragma unroll 8
                for (int kp = 0; kp < 32; kp++) {
                    z += redf[((cc * 4 + bp) * NTHR + kp * 32 + jgx) * 2 + half];
                    z += redf[((cc * 4 + bp) * NTHR + kp * 32 + 16 + jgx) * 2 + half];
                }
                int gate = gc >> 3, ch = gc & 7;
                z += __ldg(&bias[gate * 1024 + bid * 8 + ch]);
                float* zs = sm + 32768;
                zs[gc * 8 + b] = z;
            }
            __syncthreads();
            if (tid < 64) {
                int b = tid & 7, ch = tid >> 3;
                int jh = bid * 8 + ch;
                const float* zs = sm + 32768;
                float zi = zs[(0 * 8 + ch) * 8 + b];
                float zf = zs[(1 * 8 + ch) * 8 + b];
                float zg = zs[(2 * 8 + ch) * 8 + b];
                float zo = zs[(3 * 8 + ch) * 8 + b];
                float c_eff = 0.0f;
                if (!is_start) c_eff = s_adv[b] ? g_c2[p ^ 1][b * H + jh] : g_c[b * H + jh];
                g_c[b * H + jh] = c_eff;
                float cn = sigm(zf) * c_eff + sigm(zi) * tanhf(zg);
                float hn = sigm(zo) * tanhf(cn);
                g_c2[p][b * H + jh] = cn;
                g_h2[p][b * H + jh] = hn;
            }
        }
        grid_sync(bid);

        // ---- pred (blocks 0..127); block 128 resets g_afin ----
        if (bid < 128) {
            const float* h2c = g_h2[p];
#pragma unroll
            for (int bb = 0; bb < 8; bb++) {
                int k = tid;
                sm[k * 8 + bb] = h2c[bb * H + k];
            }
            __syncthreads();
            int w = tid >> 5, lane = tid & 31;
            int jloc = w & 7, q4 = w >> 3;
            int j = bid * 8 + jloc;
            const float4* wp = (const float4*)(g_WpT + (size_t)j * H + q4 * 256);
            const unsigned long long* hu = (const unsigned long long*)sm;
            float4 wA = wp[lane];
            float4 wB = wp[32 + lane];
            unsigned long long acc[4];
#pragma unroll
            for (int bp = 0; bp < 4; bp++) acc[bp] = 0ull;
#pragma unroll
            for (int cIt = 0; cIt < 2; cIt++) {
                int k = q4 * 256 + cIt * 128 + lane * 4;
                float4 w4 = (cIt == 0) ? wA : wB;
                unsigned long long w0 = dup2(w4.x), w1 = dup2(w4.y);
                unsigned long long w2 = dup2(w4.z), w3 = dup2(w4.w);
#pragma unroll
                for (int bp = 0; bp < 4; bp++) {
                    acc[bp] = ffma2(hu[(k + 0) * 4 + bp], w0, acc[bp]);
                    acc[bp] = ffma2(hu[(k + 1) * 4 + bp], w1, acc[bp]);
                    acc[bp] = ffma2(hu[(k + 2) * 4 + bp], w2, acc[bp]);
                    acc[bp] = ffma2(hu[(k + 3) * 4 + bp], w3, acc[bp]);
                }
            }
            float a[8];
#pragma unroll
            for (int bp = 0; bp < 4; bp++) {
                unsigned lo, hi;
                asm("mov.b64 {%0, %1}, %2;" : "=r"(lo), "=r"(hi) : "l"(acc[bp]));
                a[bp * 2] = __uint_as_float(lo);
                a[bp * 2 + 1] = __uint_as_float(hi);
            }
#pragma unroll
            for (int off = 16; off > 0; off >>= 1)
#pragma unroll
                for (int b = 0; b < 8; b++)
                    a[b] += __shfl_down_sync(0xffffffffu, a[b], off);
            float* prsh = sm + 8192;
            if (lane == 0) {
#pragma unroll
                for (int b = 0; b < 8; b++)
                    prsh[q4 * 64 + jloc * 8 + b] = a[b];
            }
            __syncthreads();
            if (tid < 64) {
                int jl = tid >> 3, b = tid & 7;
                int jj = bid * 8 + jl;
                int t = s >> 2;
                float v = prsh[jl * 8 + b] + prsh[64 + jl * 8 + b]
                        + prsh[128 + jl * 8 + b] + prsh[192 + jl * 8 + b]
                        + g_E[((size_t)t * B + b) * H + jj];
                float qv = tanhf(v);
                g_qbj[b * 1024 + jj] = qv;
                float qo = __shfl_xor_sync(0xffffffffu, qv, 8);
                if ((jl & 1) == 0) {
                    unsigned lo = (unsigned)__bfloat16_as_ushort(__float2bfloat16(qv));
                    unsigned hi = (unsigned)__bfloat16_as_ushort(__float2bfloat16(qo));
                    g_qmma[(bid * 4 + (jl >> 1)) * 8 + b] = (hi << 16) | lo;
                }
            }
        } else if (bid == 128) {
            if (tid < 8) g_afin[tid] = 0ull;
        }
        grid_sync(bid);

        // ---- joint: bf16 HMMA logits + block-local fp32 re-check -> exact g_afin ----
        {
            unsigned* qsm = (unsigned*)sm;               // [0,4096) u32 = q bf16 pairs
            for (int i = tid; i < 4096; i += NTHR) qsm[i] = g_qmma[i];
            __syncthreads();
            float* ppart = sm + 16384;                    // [2][8][112]
            int w = tid >> 5, lane = tid & 31;
            if (w < 28) {
                int ct = w >> 1, kh = w & 1;
                int g = lane >> 2, tig = lane & 3;
                const unsigned long long* wb = (const unsigned long long*)g_WoutM
                    + (size_t)bid * 28672 + ct * 32 + lane;
                float d0 = 0.0f, d1 = 0.0f, d2 = 0.0f, d3 = 0.0f;
                unsigned zero = 0u;
                int kt0 = kh * 32;
                unsigned long long ring[4];
#pragma unroll
                for (int i = 0; i < 4; i++) ring[i] = wb[(size_t)(kt0 + i) * 448];
#pragma unroll
                for (int kk = 0; kk < 32; kk += 4) {
#pragma unroll
                    for (int i = 0; i < 4; i++) {
                        unsigned long long bw = ring[i];
                        ring[i] = wb[(size_t)(kt0 + kk + 4 + i) * 448];
                        int kt = kt0 + kk + i;
                        unsigned a0 = qsm[(kt * 8 + tig) * 8 + g];
                        unsigned a2 = qsm[(kt * 8 + 4 + tig) * 8 + g];
                        unsigned b0 = (unsigned)bw, b1 = (unsigned)(bw >> 32);
                        asm volatile(
                            "mma.sync.aligned.m16n8k16.row.col.f32.bf16.bf16.f32 "
                            "{%0,%1,%2,%3}, {%4,%5,%6,%7}, {%8,%9}, {%0,%1,%2,%3};"
                            : "+f"(d0), "+f"(d1), "+f"(d2), "+f"(d3)
                            : "r"(a0), "r"(zero), "r"(a2), "r"(zero), "r"(b0), "r"(b1));
                    }
                }
                int col = ct * 8 + tig * 2;
                ppart[(kh * 8 + g) * JTILE + col + 0] = d0;
                ppart[(kh * 8 + g) * JTILE + col + 1] = d1;
            }
            __syncthreads();
            float* logf = sm + 33024;
            if (tid < JTILE * 8) {
                int o = tid;
                int v = bid * JTILE + (o % JTILE);
                float sv = ppart[o] + ppart[896 + o];
                logf[o] = (v < NV) ? sv + __ldg(&b_out[v]) : -1e30f;
            }
            __syncthreads();
            // block-local max per b
            float* spart = sm + 33920;
            if (tid < 64) {
                int b = tid >> 3, part = tid & 7;
                float m = -1e30f;
#pragma unroll
                for (int cc = 0; cc < 14; cc++)
                    m = fmaxf(m, logf[b * JTILE + part * 14 + cc]);
                spart[tid] = m;
            }
            __syncthreads();
            if (tid < 8) {
                float m = -1e30f;
#pragma unroll
                for (int pp = 0; pp < 8; pp++) m = fmaxf(m, spart[tid * 8 + pp]);
                s_gmax[tid] = m;
            }
            if (tid == 0) s_ncand = 0;
            __syncthreads();
            if (tid < JTILE * 8) {
                int o = tid, b = o / JTILE;
                if (logf[o] >= s_gmax[b] - DELTA) {
                    int i = atomicAdd(&s_ncand, 1);
                    s_cand[i] = (b << 16) | (bid * JTILE + (o - b * JTILE));
                }
            }
            __syncthreads();
            int nc = s_ncand;
            int w2 = tid >> 5, ln = tid & 31;
            for (int ci = w2; ci < nc; ci += 32) {
                int pk = s_cand[ci];
                int b = pk >> 16, v = pk & 0xffff;
                if (v < NV) {
                    const float* wv = g_WoutV + (size_t)v * 1024;
                    const float* qv = g_qbj + b * 1024;
                    float part = 0.0f;
#pragma unroll 8
                    for (int kk = ln; kk < 1024; kk += 32)
                        part = fmaf(wv[kk], qv[kk], part);
#pragma unroll
                    for (int off = 16; off > 0; off >>= 1)
                        part += __shfl_down_sync(0xffffffffu, part, off);
                    if (ln == 0)
                        atomicMax(&g_afin[b], pack_key(part + __ldg(&b_out[v]), v));
                }
            }
        }
        grid_sync(bid);
    }

    // ---- epilogue: final decision + h,c output ----
    {
        int d = NSTEP - 1, dp = d & 1;
        if (tid < 8) {
            int b = tid;
            unsigned long long key = g_afin[b];
            int sym = BLANK - (int)(unsigned)(key & 0xffffffffu);
            int t = d >> 2, u = d & 3;
            int active = (u == 0) ? (t < lens[b]) : g_advbuf[dp ^ 1][b];
            int advance = (active && sym != BLANK) ? 1 : 0;
            if (bid == 0)
                out[(size_t)b * NSTEP + t * MAXSYM + u] = (float)(active ? sym : BLANK);
            s_adv[tid] = advance;
        }
        __syncthreads();
        for (int i = bid * NTHR + tid; i < B * H; i += G * NTHR) {
            int b = i >> 10;
            float hf = s_adv[b] ? g_h2[dp][i] : g_h[i];
            float cf = s_adv[b] ? g_c2[dp][i] : g_c[i];
            out[B * NSTEP + i] = hf;
            out[B * NSTEP + B * H + i] = cf;
        }
    }
}

extern "C" void kernel_launch(void* const* d_in, const int* in_sizes, int n_in,
                              void* d_out, int out_size) {
    (void)in_sizes; (void)n_in; (void)out_size;
    const float* enc     = (const float*)d_in[0];
    const int*   lens    = (const int*)d_in[1];
    const float* emb     = (const float*)d_in[2];
    const float* Wx      = (const float*)d_in[3];
    const float* Wh      = (const float*)d_in[4];
    const float* bias    = (const float*)d_in[5];
    const float* W_enc   = (const float*)d_in[6];
    const float* W_pred  = (const float*)d_in[7];
    const float* b_joint = (const float*)d_in[8];
    const float* W_out   = (const float*)d_in[9];
    const float* b_out   = (const float*)d_in[10];
    float* out = (float*)d_out;

    static int configured = 0;
    if (!configured) {
        cudaFuncSetAttribute(k_decode, cudaFuncAttributeMaxDynamicSharedMemorySize,
                             SMEM_FLOATS * 4);
        configured = 1;
    }

    k_setup1<<<2816, dim3(32, 8)>>>(enc, W_pred);
    k_setup2<<<G * 64 + 128 * 1024 + 513 * 32, 448>>>(W_out, Wx, Wh);
    k_egemm<<<dim3(4, T), 256>>>(W_enc, b_joint);
    k_decode<<<G, NTHR, SMEM_FLOATS * 4>>>(emb, bias, b_out, lens, out);
}